// round 1
// baseline (speedup 1.0000x reference)
#include <cuda_runtime.h>
#include <cstdint>

#define BB   16
#define N1   4096
#define N2   1024
#define C2   256
#define OUTC 256
#define KG   4096   // GEMM K == N1

// ---------------- scratch (static device globals; no allocation) -------------
__device__ float g_w[BB * N1 * 3];
__device__ int   g_id[BB * N1 * 3];
__device__ float g_interp[(size_t)BB * N1 * C2];   // 64 MB
__device__ float g_y[BB * C2 * OUTC];              // 4 MB
__device__ float g_mean[C2];
__device__ float g_rstd[C2];

// ---------------- helpers ----------------------------------------------------
__device__ __forceinline__ void fma2(unsigned long long& d,
                                     unsigned long long a,
                                     unsigned long long b) {
    asm("fma.rn.f32x2 %0, %1, %2, %0;" : "+l"(d) : "l"(a), "l"(b));
}
__device__ __forceinline__ float2 ull_as_float2(unsigned long long v) {
    float2 r;
    asm("mov.b64 {%0, %1}, %2;" : "=f"(r.x), "=f"(r.y) : "l"(v));
    return r;
}

// ---------------- kernel 1: 3-NN + inverse-distance weights ------------------
// grid (N1/128, B), block 128
__global__ __launch_bounds__(128) void knn_kernel(const float* __restrict__ xyz1,
                                                  const float* __restrict__ xyz2) {
    __shared__ float4 q[N2];
    const int b = blockIdx.y;
    const float* x2b = xyz2 + (size_t)b * N2 * 3;
    for (int j = threadIdx.x; j < N2; j += blockDim.x) {
        float x = x2b[j * 3 + 0], y = x2b[j * 3 + 1], z = x2b[j * 3 + 2];
        q[j] = make_float4(x, y, z, x * x + y * y + z * z);
    }
    __syncthreads();

    const int n = blockIdx.x * 128 + threadIdx.x;
    const float* p = xyz1 + ((size_t)b * N1 + n) * 3;
    const float px = p[0], py = p[1], pz = p[2];
    const float pp = px * px + py * py + pz * pz;
    const float ax = -2.f * px, ay = -2.f * py, az = -2.f * pz;

    const float INF = __int_as_float(0x7f800000);
    float s0 = INF, s1 = INF, s2 = INF;
    int i0 = 0, i1 = 0, i2 = 0;

#pragma unroll 4
    for (int j = 0; j < N2; ++j) {
        float4 Q = q[j];
        float s = fmaf(ax, Q.x, fmaf(ay, Q.y, fmaf(az, Q.z, Q.w)));
        if (s < s2) {
            if (s < s1) {
                s2 = s1; i2 = i1;
                if (s < s0) { s1 = s0; i1 = i0; s0 = s; i0 = j; }
                else        { s1 = s;  i1 = j; }
            } else { s2 = s; i2 = j; }
        }
    }
    float d0 = s0 + pp, d1 = s1 + pp, d2 = s2 + pp;
    float r0 = 1.f / (d0 + 1e-8f), r1 = 1.f / (d1 + 1e-8f), r2 = 1.f / (d2 + 1e-8f);
    float rs = 1.f / (r0 + r1 + r2);
    size_t base = ((size_t)b * N1 + n) * 3;
    g_w[base + 0] = r0 * rs;  g_w[base + 1] = r1 * rs;  g_w[base + 2] = r2 * rs;
    g_id[base + 0] = i0;      g_id[base + 1] = i1;      g_id[base + 2] = i2;
}

// ---------------- kernel 2: gather + interpolate ------------------------------
// grid (N1/4, B), block 256 : 4 points x 64 float4-lanes
__global__ __launch_bounds__(256) void interp_kernel(const float* __restrict__ x2) {
    const int b  = blockIdx.y;
    const int nl = threadIdx.x >> 6;
    const int c4 = (threadIdx.x & 63) << 2;
    const int n  = blockIdx.x * 4 + nl;

    const size_t base = ((size_t)b * N1 + n) * 3;
    const int i0 = g_id[base], i1 = g_id[base + 1], i2 = g_id[base + 2];
    const float w0 = g_w[base], w1 = g_w[base + 1], w2 = g_w[base + 2];

    const float* xb = x2 + (size_t)b * N2 * C2;
    float4 v0 = *(const float4*)(xb + (size_t)i0 * C2 + c4);
    float4 v1 = *(const float4*)(xb + (size_t)i1 * C2 + c4);
    float4 v2 = *(const float4*)(xb + (size_t)i2 * C2 + c4);
    float4 r;
    r.x = w0 * v0.x + w1 * v1.x + w2 * v2.x;
    r.y = w0 * v0.y + w1 * v1.y + w2 * v2.y;
    r.z = w0 * v0.z + w1 * v1.z + w2 * v2.z;
    r.w = w0 * v0.w + w1 * v1.w + w2 * v2.w;
    *(float4*)(g_interp + ((size_t)b * N1 + n) * C2 + c4) = r;
}

// ---------------- kernel 3: per-batch SGEMM (FFMA2 / f32x2) -------------------
// y[b,c,o] = sum_n interp[b,n,c] * W1[o,n] + b1[o]
// A = interp[b] laid out [k=4096][m=256] (m contiguous); B = W1 [n=256][k=4096]
// 64x64 tile, BK=16, 256 threads, per-thread 4(m) x 4(n) via packed f32x2 pairs
// along m. Bs holds duplicated {b,b} pairs so the hot loop needs no packing movs.
#define BM 64
#define BN 64
#define BK 16
#define A_LD 68   // padded row (floats)
#define B_LD 66   // padded row (float2)

__global__ __launch_bounds__(256) void gemm_kernel(const float* __restrict__ W1,
                                                   const float* __restrict__ b1) {
    __shared__ __align__(16) float  As[2][BK][A_LD];
    __shared__ __align__(16) float2 Bs[2][BK][B_LD];

    const int b  = blockIdx.y;
    const int mt = blockIdx.x & 3;
    const int nt = blockIdx.x >> 2;

    const float* A  = g_interp + (size_t)b * N1 * C2 + mt * BM;  // ldA = 256
    const float* Bw = W1 + (size_t)(nt * BN) * KG;               // ldB = 4096
    float* C = g_y + (size_t)b * C2 * OUTC;

    const int tid = threadIdx.x;
    const int tm = tid & 15, tn = tid >> 4;

    const int akk = tid >> 4, ac4 = (tid & 15) << 2;   // A loader coords
    const int bo  = tid >> 2, bkq = (tid & 3) << 2;    // B loader coords

    unsigned long long acc[2][4];
#pragma unroll
    for (int i = 0; i < 2; ++i)
#pragma unroll
        for (int j = 0; j < 4; ++j) acc[i][j] = 0ull;

    float4 av = *(const float4*)(A + (size_t)akk * C2 + ac4);
    float4 bv = *(const float4*)(Bw + (size_t)bo * KG + bkq);
    *(float4*)&As[0][akk][ac4] = av;
    Bs[0][bkq + 0][bo] = make_float2(bv.x, bv.x);
    Bs[0][bkq + 1][bo] = make_float2(bv.y, bv.y);
    Bs[0][bkq + 2][bo] = make_float2(bv.z, bv.z);
    Bs[0][bkq + 3][bo] = make_float2(bv.w, bv.w);
    __syncthreads();

    const int KT = KG / BK;   // 256
    for (int kt = 0; kt < KT; ++kt) {
        const int s = kt & 1;
        if (kt + 1 < KT) {
            const int k0 = (kt + 1) * BK;
            av = *(const float4*)(A + (size_t)(k0 + akk) * C2 + ac4);
            bv = *(const float4*)(Bw + (size_t)bo * KG + k0 + bkq);
        }
#pragma unroll
        for (int kk = 0; kk < BK; ++kk) {
            ulonglong2 a   = *(const ulonglong2*)&As[s][kk][tm * 4];      // {a0,a1},{a2,a3}
            ulonglong2 b01 = *(const ulonglong2*)&Bs[s][kk][tn * 4];      // {b0,b0},{b1,b1}
            ulonglong2 b23 = *(const ulonglong2*)&Bs[s][kk][tn * 4 + 2];  // {b2,b2},{b3,b3}
            fma2(acc[0][0], a.x, b01.x);  fma2(acc[0][1], a.x, b01.y);
            fma2(acc[0][2], a.x, b23.x);  fma2(acc[0][3], a.x, b23.y);
            fma2(acc[1][0], a.y, b01.x);  fma2(acc[1][1], a.y, b01.y);
            fma2(acc[1][2], a.y, b23.x);  fma2(acc[1][3], a.y, b23.y);
        }
        if (kt + 1 < KT) {
            const int d = s ^ 1;
            *(float4*)&As[d][akk][ac4] = av;
            Bs[d][bkq + 0][bo] = make_float2(bv.x, bv.x);
            Bs[d][bkq + 1][bo] = make_float2(bv.y, bv.y);
            Bs[d][bkq + 2][bo] = make_float2(bv.z, bv.z);
            Bs[d][bkq + 3][bo] = make_float2(bv.w, bv.w);
            __syncthreads();
        }
    }

    const int m0 = mt * BM + tm * 4;
    const int n0 = nt * BN + tn * 4;
    const float4 bias = *(const float4*)(b1 + n0);
#pragma unroll
    for (int mp = 0; mp < 2; ++mp) {
        float2 p0 = ull_as_float2(acc[mp][0]);
        float2 p1 = ull_as_float2(acc[mp][1]);
        float2 p2 = ull_as_float2(acc[mp][2]);
        float2 p3 = ull_as_float2(acc[mp][3]);
        float4 lo = make_float4(p0.x + bias.x, p1.x + bias.y, p2.x + bias.z, p3.x + bias.w);
        float4 hi = make_float4(p0.y + bias.x, p1.y + bias.y, p2.y + bias.z, p3.y + bias.w);
        *(float4*)(C + (size_t)(m0 + 2 * mp)     * OUTC + n0) = lo;
        *(float4*)(C + (size_t)(m0 + 2 * mp + 1) * OUTC + n0) = hi;
    }
}

// ---------------- kernel 4: BN batch stats per channel c ---------------------
// grid 256 (c), block 256 (o); reduce over b (16) and o (256) = 4096 values
__global__ __launch_bounds__(256) void stats_kernel() {
    const int c = blockIdx.x;
    const int o = threadIdx.x;
    float s = 0.f, s2 = 0.f;
#pragma unroll
    for (int b = 0; b < BB; ++b) {
        float v = g_y[((size_t)b * C2 + c) * OUTC + o];
        s += v;
        s2 = fmaf(v, v, s2);
    }
    __shared__ float rs[256], rq[256];
    rs[o] = s; rq[o] = s2;
    __syncthreads();
    for (int st = 128; st > 0; st >>= 1) {
        if (o < st) { rs[o] += rs[o + st]; rq[o] += rq[o + st]; }
        __syncthreads();
    }
    if (o == 0) {
        float mean = rs[0] * (1.f / 4096.f);
        float var  = rq[0] * (1.f / 4096.f) - mean * mean;
        g_mean[c] = mean;
        g_rstd[c] = rsqrtf(var + 1e-5f);
    }
}

// ---------------- kernel 5: BN apply + ReLU + transpose ----------------------
// out[b,o,c] = relu(gamma[c]*(y[b,c,o]-mean[c])*rstd[c] + beta[c])
// grid (8,8,B), block (32,8); 32x32 smem tile transpose
__global__ void epilogue_kernel(const float* __restrict__ gamma,
                                const float* __restrict__ beta,
                                float* __restrict__ out) {
    __shared__ float tile[32][33];
    const int b = blockIdx.z, c0 = blockIdx.x * 32, o0 = blockIdx.y * 32;
    const int tx = threadIdx.x, ty = threadIdx.y;
#pragma unroll
    for (int i = 0; i < 4; ++i) {
        int c = c0 + ty + i * 8;
        float v = g_y[((size_t)b * C2 + c) * OUTC + o0 + tx];
        v = fmaf(gamma[c] * g_rstd[c], v - g_mean[c], beta[c]);
        tile[ty + i * 8][tx] = fmaxf(v, 0.f);
    }
    __syncthreads();
#pragma unroll
    for (int i = 0; i < 4; ++i) {
        int o = o0 + ty + i * 8;
        out[((size_t)b * OUTC + o) * C2 + c0 + tx] = tile[tx][ty + i * 8];
    }
}

// ---------------- launch ------------------------------------------------------
extern "C" void kernel_launch(void* const* d_in, const int* in_sizes, int n_in,
                              void* d_out, int out_size) {
    // metadata order: x1, x2, xyz1, xyz2, W1, b1, gamma, beta  (x1 unused)
    const float* x2    = (const float*)d_in[1];
    const float* xyz1  = (const float*)d_in[2];
    const float* xyz2  = (const float*)d_in[3];
    const float* W1    = (const float*)d_in[4];
    const float* b1    = (const float*)d_in[5];
    const float* gamma = (const float*)d_in[6];
    const float* beta  = (const float*)d_in[7];
    float* out = (float*)d_out;

    knn_kernel<<<dim3(N1 / 128, BB), 128>>>(xyz1, xyz2);
    interp_kernel<<<dim3(N1 / 4, BB), 256>>>(x2);
    gemm_kernel<<<dim3(16, BB), 256>>>(W1, b1);
    stats_kernel<<<C2, 256>>>();
    epilogue_kernel<<<dim3(8, 8, BB), dim3(32, 8)>>>(gamma, beta, out);
}

// round 2
// speedup vs baseline: 2.2971x; 2.2971x over previous
#include <cuda_runtime.h>
#include <cstdint>

#define BB   16
#define N1   4096
#define N2   1024
#define C2   256
#define OUTC 256
#define KG   4096
#define NNZ  (N1 * 3)          // 12288 list slots per batch

// ---------------- scratch (static device globals; no allocation) -------------
__device__ float g_w[BB * N1 * 3];
__device__ int   g_id[BB * N1 * 3];
__device__ int   g_cnt[BB * N2];           // histogram (zeroed each launch)
__device__ int   g_off[BB * N2];           // CSC start offsets
__device__ int   g_cur[BB * N2];           // fill cursors; == end after fill
__device__ int   g_ln[BB * NNZ];           // CSC: source n index
__device__ float g_lw[BB * NNZ];           // CSC: weight
__device__ float g_W1T[(size_t)KG * OUTC]; // W1 transposed [n][o]
__device__ float g_T[(size_t)BB * N2 * OUTC];  // 16 MB: T[b,m,o]
__device__ float g_y[BB * C2 * OUTC];
__device__ float g_mean[C2];
__device__ float g_rstd[C2];

// ---------------- helpers ----------------------------------------------------
__device__ __forceinline__ void fma2(unsigned long long& d,
                                     unsigned long long a,
                                     unsigned long long b) {
    asm("fma.rn.f32x2 %0, %1, %2, %0;" : "+l"(d) : "l"(a), "l"(b));
}
__device__ __forceinline__ float2 ull_as_float2(unsigned long long v) {
    float2 r;
    asm("mov.b64 {%0, %1}, %2;" : "=f"(r.x), "=f"(r.y) : "l"(v));
    return r;
}

// ---------------- kernel 0: zero histogram -----------------------------------
__global__ void zero_kernel() {
    int i = blockIdx.x * 256 + threadIdx.x;
    if (i < BB * N2) g_cnt[i] = 0;
}

// ---------------- kernel 1: 3-NN + weights + degree histogram ----------------
__global__ __launch_bounds__(128) void knn_kernel(const float* __restrict__ xyz1,
                                                  const float* __restrict__ xyz2) {
    __shared__ float4 q[N2];
    const int b = blockIdx.y;
    const float* x2b = xyz2 + (size_t)b * N2 * 3;
    for (int j = threadIdx.x; j < N2; j += blockDim.x) {
        float x = x2b[j * 3 + 0], y = x2b[j * 3 + 1], z = x2b[j * 3 + 2];
        q[j] = make_float4(x, y, z, x * x + y * y + z * z);
    }
    __syncthreads();

    const int n = blockIdx.x * 128 + threadIdx.x;
    const float* p = xyz1 + ((size_t)b * N1 + n) * 3;
    const float px = p[0], py = p[1], pz = p[2];
    const float pp = px * px + py * py + pz * pz;
    const float ax = -2.f * px, ay = -2.f * py, az = -2.f * pz;

    const float INF = __int_as_float(0x7f800000);
    float s0 = INF, s1 = INF, s2 = INF;
    int i0 = 0, i1 = 0, i2 = 0;

#pragma unroll 4
    for (int j = 0; j < N2; ++j) {
        float4 Q = q[j];
        float s = fmaf(ax, Q.x, fmaf(ay, Q.y, fmaf(az, Q.z, Q.w)));
        if (s < s2) {
            if (s < s1) {
                s2 = s1; i2 = i1;
                if (s < s0) { s1 = s0; i1 = i0; s0 = s; i0 = j; }
                else        { s1 = s;  i1 = j; }
            } else { s2 = s; i2 = j; }
        }
    }
    float d0 = s0 + pp, d1 = s1 + pp, d2 = s2 + pp;
    float r0 = 1.f / (d0 + 1e-8f), r1 = 1.f / (d1 + 1e-8f), r2 = 1.f / (d2 + 1e-8f);
    float rs = 1.f / (r0 + r1 + r2);
    size_t base = ((size_t)b * N1 + n) * 3;
    g_w[base + 0] = r0 * rs;  g_w[base + 1] = r1 * rs;  g_w[base + 2] = r2 * rs;
    g_id[base + 0] = i0;      g_id[base + 1] = i1;      g_id[base + 2] = i2;
    atomicAdd(&g_cnt[b * N2 + i0], 1);
    atomicAdd(&g_cnt[b * N2 + i1], 1);
    atomicAdd(&g_cnt[b * N2 + i2], 1);
}

// ---------------- kernel 2: per-batch exclusive scan of degrees --------------
// grid BB, block 256; each thread handles 4 counters
__global__ __launch_bounds__(256) void scan_kernel() {
    const int b = blockIdx.x, t = threadIdx.x;
    const int base = b * N2 + t * 4;
    int v0 = g_cnt[base], v1 = g_cnt[base + 1], v2 = g_cnt[base + 2], v3 = g_cnt[base + 3];
    int tsum = v0 + v1 + v2 + v3;
    __shared__ int ps[256];
    ps[t] = tsum;
    __syncthreads();
    for (int st = 1; st < 256; st <<= 1) {
        int a = (t >= st) ? ps[t - st] : 0;
        __syncthreads();
        ps[t] += a;
        __syncthreads();
    }
    int o0 = ps[t] - tsum;   // exclusive
    g_off[base + 0] = o0; g_cur[base + 0] = o0; o0 += v0;
    g_off[base + 1] = o0; g_cur[base + 1] = o0; o0 += v1;
    g_off[base + 2] = o0; g_cur[base + 2] = o0; o0 += v2;
    g_off[base + 3] = o0; g_cur[base + 3] = o0;
}

// ---------------- kernel 3: CSC fill ------------------------------------------
__global__ __launch_bounds__(256) void fill_kernel() {
    const int b = blockIdx.y;
    const int n = blockIdx.x * 256 + threadIdx.x;
    const size_t base = ((size_t)b * N1 + n) * 3;
    const int lbase = b * NNZ;
#pragma unroll
    for (int j = 0; j < 3; ++j) {
        int   m = g_id[base + j];
        float w = g_w[base + j];
        int pos = atomicAdd(&g_cur[b * N2 + m], 1);
        g_ln[lbase + pos] = n;
        g_lw[lbase + pos] = w;
    }
}

// ---------------- kernel 4: transpose W1 -> W1T [n][o] ------------------------
__global__ void w1t_kernel(const float* __restrict__ W1) {
    __shared__ float tile[32][33];
    const int n0 = blockIdx.x * 32, o0 = blockIdx.y * 32;
    const int tx = threadIdx.x, ty = threadIdx.y;
#pragma unroll
    for (int i = 0; i < 4; ++i)
        tile[ty + i * 8][tx] = W1[(size_t)(o0 + ty + i * 8) * KG + n0 + tx];
    __syncthreads();
#pragma unroll
    for (int i = 0; i < 4; ++i)
        g_W1T[(size_t)(n0 + ty + i * 8) * OUTC + o0 + tx] = tile[tx][ty + i * 8];
}

// ---------------- kernel 5: build T[b,m,o] = sum_list w * W1T[n,o] ------------
// grid (N2, BB), block 256 (one thread per o)
__global__ __launch_bounds__(256) void tbuild_kernel() {
    const int b = blockIdx.y, m = blockIdx.x, o = threadIdx.x;
    const int s0 = g_off[b * N2 + m];
    const int s1 = g_cur[b * N2 + m];   // == end after fill
    const int lbase = b * NNZ;
    __shared__ int   sn[256];
    __shared__ float swt[256];
    float acc = 0.f;
    for (int s = s0; s < s1; s += 256) {
        int c = min(256, s1 - s);
        __syncthreads();
        if (o < c) { sn[o] = g_ln[lbase + s + o]; swt[o] = g_lw[lbase + s + o]; }
        __syncthreads();
        for (int i = 0; i < c; ++i)
            acc = fmaf(swt[i], g_W1T[(size_t)sn[i] * OUTC + o], acc);
    }
    g_T[((size_t)b * N2 + m) * OUTC + o] = acc;
}

// ---------------- kernel 6: per-batch SGEMM, K=1024 (FFMA2) -------------------
// y[b,c,o] = sum_m x2[b,m,c] * T[b,m,o] + b1[o]
// A = x2[b]  [m=1024][c=256]  (k-major), B = T[b] [m=1024][o=256] (k-major)
#define BM 64
#define BN 64
#define BK 16
#define A_LD 68   // padded row (floats)
#define B_LD 66   // padded row (float2)

__global__ __launch_bounds__(256) void gemm_kernel(const float* __restrict__ x2,
                                                   const float* __restrict__ b1) {
    __shared__ __align__(16) float  As[2][BK][A_LD];
    __shared__ __align__(16) float2 Bs[2][BK][B_LD];

    const int b  = blockIdx.y;
    const int mt = blockIdx.x & 3;    // c tile
    const int nt = blockIdx.x >> 2;   // o tile

    const float* A  = x2  + (size_t)b * N2 * C2   + mt * BM;   // ld 256
    const float* Bw = g_T + (size_t)b * N2 * OUTC + nt * BN;   // ld 256
    float* C = g_y + (size_t)b * C2 * OUTC;

    const int tid = threadIdx.x;
    const int tm = tid & 15, tn = tid >> 4;

    const int akk = tid >> 4, ac4 = (tid & 15) << 2;   // A loader: 16 rows x 64
    const int bk8 = tid >> 5, bo2 = (tid & 31) << 1;   // B loader: 8 rows/pass x 64

    unsigned long long acc[2][4];
#pragma unroll
    for (int i = 0; i < 2; ++i)
#pragma unroll
        for (int j = 0; j < 4; ++j) acc[i][j] = 0ull;

    float4 av  = *(const float4*)(A  + (size_t)akk * C2 + ac4);
    float2 bv0 = *(const float2*)(Bw + (size_t)bk8       * OUTC + bo2);
    float2 bv1 = *(const float2*)(Bw + (size_t)(bk8 + 8) * OUTC + bo2);
    *(float4*)&As[0][akk][ac4]     = av;
    *(float4*)&Bs[0][bk8][bo2]     = make_float4(bv0.x, bv0.x, bv0.y, bv0.y);
    *(float4*)&Bs[0][bk8 + 8][bo2] = make_float4(bv1.x, bv1.x, bv1.y, bv1.y);
    __syncthreads();

    const int KT = N2 / BK;   // 64
    for (int kt = 0; kt < KT; ++kt) {
        const int s = kt & 1;
        if (kt + 1 < KT) {
            const int k0 = (kt + 1) * BK;
            av  = *(const float4*)(A  + (size_t)(k0 + akk) * C2 + ac4);
            bv0 = *(const float2*)(Bw + (size_t)(k0 + bk8)     * OUTC + bo2);
            bv1 = *(const float2*)(Bw + (size_t)(k0 + bk8 + 8) * OUTC + bo2);
        }
#pragma unroll
        for (int kk = 0; kk < BK; ++kk) {
            ulonglong2 a   = *(const ulonglong2*)&As[s][kk][tm * 4];
            ulonglong2 b01 = *(const ulonglong2*)&Bs[s][kk][tn * 4];
            ulonglong2 b23 = *(const ulonglong2*)&Bs[s][kk][tn * 4 + 2];
            fma2(acc[0][0], a.x, b01.x);  fma2(acc[0][1], a.x, b01.y);
            fma2(acc[0][2], a.x, b23.x);  fma2(acc[0][3], a.x, b23.y);
            fma2(acc[1][0], a.y, b01.x);  fma2(acc[1][1], a.y, b01.y);
            fma2(acc[1][2], a.y, b23.x);  fma2(acc[1][3], a.y, b23.y);
        }
        if (kt + 1 < KT) {
            const int d = s ^ 1;
            *(float4*)&As[d][akk][ac4]     = av;
            *(float4*)&Bs[d][bk8][bo2]     = make_float4(bv0.x, bv0.x, bv0.y, bv0.y);
            *(float4*)&Bs[d][bk8 + 8][bo2] = make_float4(bv1.x, bv1.x, bv1.y, bv1.y);
            __syncthreads();
        }
    }

    const int m0 = mt * BM + tm * 4;   // c
    const int n0 = nt * BN + tn * 4;   // o
    const float4 bias = *(const float4*)(b1 + n0);
#pragma unroll
    for (int mp = 0; mp < 2; ++mp) {
        float2 p0 = ull_as_float2(acc[mp][0]);
        float2 p1 = ull_as_float2(acc[mp][1]);
        float2 p2 = ull_as_float2(acc[mp][2]);
        float2 p3 = ull_as_float2(acc[mp][3]);
        float4 lo = make_float4(p0.x + bias.x, p1.x + bias.y, p2.x + bias.z, p3.x + bias.w);
        float4 hi = make_float4(p0.y + bias.x, p1.y + bias.y, p2.y + bias.z, p3.y + bias.w);
        *(float4*)(C + (size_t)(m0 + 2 * mp)     * OUTC + n0) = lo;
        *(float4*)(C + (size_t)(m0 + 2 * mp + 1) * OUTC + n0) = hi;
    }
}

// ---------------- kernel 7: BN batch stats ------------------------------------
__global__ __launch_bounds__(256) void stats_kernel() {
    const int c = blockIdx.x;
    const int o = threadIdx.x;
    float s = 0.f, s2 = 0.f;
#pragma unroll
    for (int b = 0; b < BB; ++b) {
        float v = g_y[((size_t)b * C2 + c) * OUTC + o];
        s += v;
        s2 = fmaf(v, v, s2);
    }
    __shared__ float rs[256], rq[256];
    rs[o] = s; rq[o] = s2;
    __syncthreads();
    for (int st = 128; st > 0; st >>= 1) {
        if (o < st) { rs[o] += rs[o + st]; rq[o] += rq[o + st]; }
        __syncthreads();
    }
    if (o == 0) {
        float mean = rs[0] * (1.f / 4096.f);
        float var  = rq[0] * (1.f / 4096.f) - mean * mean;
        g_mean[c] = mean;
        g_rstd[c] = rsqrtf(var + 1e-5f);
    }
}

// ---------------- kernel 8: BN apply + ReLU + transpose -----------------------
__global__ void epilogue_kernel(const float* __restrict__ gamma,
                                const float* __restrict__ beta,
                                float* __restrict__ out) {
    __shared__ float tile[32][33];
    const int b = blockIdx.z, c0 = blockIdx.x * 32, o0 = blockIdx.y * 32;
    const int tx = threadIdx.x, ty = threadIdx.y;
#pragma unroll
    for (int i = 0; i < 4; ++i) {
        int c = c0 + ty + i * 8;
        float v = g_y[((size_t)b * C2 + c) * OUTC + o0 + tx];
        v = fmaf(gamma[c] * g_rstd[c], v - g_mean[c], beta[c]);
        tile[ty + i * 8][tx] = fmaxf(v, 0.f);
    }
    __syncthreads();
#pragma unroll
    for (int i = 0; i < 4; ++i) {
        int o = o0 + ty + i * 8;
        out[((size_t)b * OUTC + o) * C2 + c0 + tx] = tile[tx][ty + i * 8];
    }
}

// ---------------- launch ------------------------------------------------------
extern "C" void kernel_launch(void* const* d_in, const int* in_sizes, int n_in,
                              void* d_out, int out_size) {
    const float* x2    = (const float*)d_in[1];
    const float* xyz1  = (const float*)d_in[2];
    const float* xyz2  = (const float*)d_in[3];
    const float* W1    = (const float*)d_in[4];
    const float* b1    = (const float*)d_in[5];
    const float* gamma = (const float*)d_in[6];
    const float* beta  = (const float*)d_in[7];
    float* out = (float*)d_out;

    zero_kernel<<<(BB * N2 + 255) / 256, 256>>>();
    knn_kernel<<<dim3(N1 / 128, BB), 128>>>(xyz1, xyz2);
    scan_kernel<<<BB, 256>>>();
    fill_kernel<<<dim3(N1 / 256, BB), 256>>>();
    w1t_kernel<<<dim3(KG / 32, OUTC / 32), dim3(32, 8)>>>(W1);
    tbuild_kernel<<<dim3(N2, BB), 256>>>();
    gemm_kernel<<<dim3(16, BB), 256>>>(x2, b1);
    stats_kernel<<<C2, 256>>>();
    epilogue_kernel<<<dim3(8, 8, BB), dim3(32, 8)>>>(gamma, beta, out);
}

// round 4
// speedup vs baseline: 2.3239x; 1.0117x over previous
#include <cuda_runtime.h>
#include <cstdint>

#define BB   16
#define N1   4096
#define N2   1024
#define C2   256
#define OUTC 256
#define KG   4096
#define NNZ  (N1 * 3)

// ---------------- scratch ------------------------------------------------------
__device__ float4 g_wi[BB * N1];               // (w0,w1,w2, packed ids)
__device__ int   g_cnt[BB * N2];
__device__ int   g_off[BB * N2];
__device__ int   g_cur[BB * N2];
__device__ int   g_ln[BB * NNZ];
__device__ float g_lw[BB * NNZ];
__device__ float g_W1T[(size_t)KG * OUTC];
__device__ float g_T[(size_t)BB * N2 * OUTC];
__device__ float g_y[BB * C2 * OUTC];
__device__ float g_mean[C2];
__device__ float g_rstd[C2];

__device__ __forceinline__ uint32_t smem_u32(const void* p) {
    uint32_t a;
    asm("{ .reg .u64 t; cvta.to.shared.u64 t, %1; cvt.u32.u64 %0, t; }" : "=r"(a) : "l"(p));
    return a;
}

// ---------------- kernel 0: zero histogram -------------------------------------
__global__ void zero_kernel() {
    int i = blockIdx.x * 256 + threadIdx.x;
    if (i < BB * N2) g_cnt[i] = 0;
}

// ---------------- kernel 1: 3-NN + weights + histogram -------------------------
__global__ __launch_bounds__(256) void knn_kernel(const float* __restrict__ xyz1,
                                                  const float* __restrict__ xyz2) {
    __shared__ float4 q[N2];
    const int b = blockIdx.y;
    const float* x2b = xyz2 + (size_t)b * N2 * 3;
    for (int j = threadIdx.x; j < N2; j += blockDim.x) {
        float x = x2b[j * 3 + 0], y = x2b[j * 3 + 1], z = x2b[j * 3 + 2];
        q[j] = make_float4(x, y, z, x * x + y * y + z * z);
    }
    __syncthreads();

    const int n = blockIdx.x * 256 + threadIdx.x;
    const float* p = xyz1 + ((size_t)b * N1 + n) * 3;
    const float px = p[0], py = p[1], pz = p[2];
    const float pp = px * px + py * py + pz * pz;
    const float ax = -2.f * px, ay = -2.f * py, az = -2.f * pz;

    const float INF = __int_as_float(0x7f800000);
    float s0 = INF, s1 = INF, s2 = INF;
    int i0 = 0, i1 = 0, i2 = 0;

#pragma unroll 8
    for (int j = 0; j < N2; ++j) {
        float4 Q = q[j];
        float s = fmaf(ax, Q.x, fmaf(ay, Q.y, fmaf(az, Q.z, Q.w)));
        if (s < s2) {
            if (s < s1) {
                s2 = s1; i2 = i1;
                if (s < s0) { s1 = s0; i1 = i0; s0 = s; i0 = j; }
                else        { s1 = s;  i1 = j; }
            } else { s2 = s; i2 = j; }
        }
    }
    float d0 = s0 + pp, d1 = s1 + pp, d2 = s2 + pp;
    float r0 = 1.f / (d0 + 1e-8f), r1 = 1.f / (d1 + 1e-8f), r2 = 1.f / (d2 + 1e-8f);
    float rs = 1.f / (r0 + r1 + r2);
    int packed = i0 | (i1 << 10) | (i2 << 20);
    g_wi[b * N1 + n] = make_float4(r0 * rs, r1 * rs, r2 * rs, __int_as_float(packed));
    atomicAdd(&g_cnt[b * N2 + i0], 1);
    atomicAdd(&g_cnt[b * N2 + i1], 1);
    atomicAdd(&g_cnt[b * N2 + i2], 1);
}

// ---------------- kernel 2: per-batch exclusive scan ----------------------------
__global__ __launch_bounds__(256) void scan_kernel() {
    const int b = blockIdx.x, t = threadIdx.x;
    const int base = b * N2 + t * 4;
    int v0 = g_cnt[base], v1 = g_cnt[base + 1], v2 = g_cnt[base + 2], v3 = g_cnt[base + 3];
    int tsum = v0 + v1 + v2 + v3;
    __shared__ int ps[256];
    ps[t] = tsum;
    __syncthreads();
    for (int st = 1; st < 256; st <<= 1) {
        int a = (t >= st) ? ps[t - st] : 0;
        __syncthreads();
        ps[t] += a;
        __syncthreads();
    }
    int o0 = ps[t] - tsum;
    g_off[base + 0] = o0; g_cur[base + 0] = o0; o0 += v0;
    g_off[base + 1] = o0; g_cur[base + 1] = o0; o0 += v1;
    g_off[base + 2] = o0; g_cur[base + 2] = o0; o0 += v2;
    g_off[base + 3] = o0; g_cur[base + 3] = o0;
}

// ---------------- kernel 3: CSC fill --------------------------------------------
__global__ __launch_bounds__(256) void fill_kernel() {
    const int b = blockIdx.y;
    const int n = blockIdx.x * 256 + threadIdx.x;
    float4 wi = g_wi[b * N1 + n];
    int packed = __float_as_int(wi.w);
    int id[3] = { packed & 1023, (packed >> 10) & 1023, (packed >> 20) & 1023 };
    float w[3] = { wi.x, wi.y, wi.z };
    const int lbase = b * NNZ;
#pragma unroll
    for (int j = 0; j < 3; ++j) {
        int pos = atomicAdd(&g_cur[b * N2 + id[j]], 1);
        g_ln[lbase + pos] = n;
        g_lw[lbase + pos] = w[j];
    }
}

// ---------------- kernel 4: transpose W1 -> W1T ---------------------------------
__global__ void w1t_kernel(const float* __restrict__ W1) {
    __shared__ float tile[32][33];
    const int n0 = blockIdx.x * 32, o0 = blockIdx.y * 32;
    const int tx = threadIdx.x, ty = threadIdx.y;
#pragma unroll
    for (int i = 0; i < 4; ++i)
        tile[ty + i * 8][tx] = W1[(size_t)(o0 + ty + i * 8) * KG + n0 + tx];
    __syncthreads();
#pragma unroll
    for (int i = 0; i < 4; ++i)
        g_W1T[(size_t)(n0 + ty + i * 8) * OUTC + o0 + tx] = tile[tx][ty + i * 8];
}

// ---------------- kernel 5: build T[b,m,o] ---------------------------------------
__global__ __launch_bounds__(256) void tbuild_kernel() {
    const int b = blockIdx.y, m = blockIdx.x, o = threadIdx.x;
    const int s0 = g_off[b * N2 + m];
    const int s1 = g_cur[b * N2 + m];
    const int lbase = b * NNZ;
    __shared__ int   sn[256];
    __shared__ float swt[256];
    float acc = 0.f;
    for (int s = s0; s < s1; s += 256) {
        int c = min(256, s1 - s);
        __syncthreads();
        if (o < c) { sn[o] = g_ln[lbase + s + o]; swt[o] = g_lw[lbase + s + o]; }
        __syncthreads();
#pragma unroll 4
        for (int i = 0; i < c; ++i)
            acc = fmaf(swt[i], g_W1T[(size_t)sn[i] * OUTC + o], acc);
    }
    g_T[((size_t)b * N2 + m) * OUTC + o] = acc;
}

// ---------------- kernel 6: mma.sync bf16 split-3 GEMM ---------------------------
// C[c,o] = sum_k A[c,k]*B[o,k]; A[c,k]=x2[b,k,c0+c], B[o,k]=T[b,k,o0+o]; K=1024
// Block 128x128, 4 warps (64x64 each). BK=32 (two k16 sub-tiles), double buffered.
// SMEM per k16 tile: 128 rows x 16 words (64B dense) with 16B-granule XOR swizzle.
// Row layout (per k16): chunk t (t=0..3) words 4t..4t+3 = [h(k=2t,2t+1), l(same),
// h(k=2t+8,2t+9), l(same)] -> one ld.shared.v4 per fragment-half, conflict-free.
#define TILE_B 8192            // 128*16*4
#define NSTAGE 32              // K/32

#define MMA_BF16(d, A0, A1, A2, A3, B0, B1)                                     \
    asm volatile("mma.sync.aligned.m16n8k16.row.col.f32.bf16.bf16.f32 "         \
        "{%0,%1,%2,%3}, {%4,%5,%6,%7}, {%8,%9}, {%0,%1,%2,%3};"                 \
        : "+f"((d)[0]), "+f"((d)[1]), "+f"((d)[2]), "+f"((d)[3])                \
        : "r"(A0), "r"(A1), "r"(A2), "r"(A3), "r"(B0), "r"(B1))

__device__ __forceinline__ uint32_t sw_addr(uint32_t base, int row, int w) {
    return base + (uint32_t)(row * 16 + (w ^ ((row & 3) << 2))) * 4u;
}

__global__ __launch_bounds__(128, 1) void gemm_mma_kernel(const float* __restrict__ x2,
                                                          const float* __restrict__ b1) {
    extern __shared__ char dyn[];
    const uint32_t sb = smem_u32(dyn);

    const int b  = blockIdx.y;
    const int c0 = (blockIdx.x & 1) * 128;
    const int o0 = (blockIdx.x >> 1) * 128;

    const int tid  = threadIdx.x;
    const int lane = tid & 31;
    const int wid  = tid >> 5;
    const int wm   = wid & 1;     // 64-row (c) half
    const int wn   = wid >> 1;    // 64-col (o) half
    const int g    = lane >> 2;   // fragment group row
    const int tq   = lane & 3;    // fragment chunk

    const float* Ab = x2  + (size_t)b * N2 * C2   + c0;
    const float* Bb = g_T + (size_t)b * N2 * OUTC + o0;

    // loader coords: 8 k-pairs x 16 col-lanes; cols stride-16 for conflict-free-ish STS
    const int lp = tid >> 4;                 // 0..7 -> k rows {2j, 2j+1} (+8 if lp>=4)
    const int ls = tid & 15;                 // col lane
    const int lj = lp & 3;
    const int ldd = (lp >> 2) * 2;           // word offset within chunk
    const int krow = 2 * lj + (lp >> 2) * 8;

    float acc[4][8][4];
#pragma unroll
    for (int mi = 0; mi < 4; ++mi)
#pragma unroll
        for (int ni = 0; ni < 8; ++ni)
#pragma unroll
            for (int r = 0; r < 4; ++r) acc[mi][ni][r] = 0.f;

    // ---- stage loader: mat(A/B) x half(k16) x 8 cols each ----
    auto load_stage = [&](int ks, int buf) {
#pragma unroll
        for (int slot = 0; slot < 4; ++slot) {
            const int half = slot & 1, mat = slot >> 1;
            const float* src = mat ? Bb : Ab;
            const int kg = ks * 32 + half * 16 + krow;
            const float* r0 = src + (size_t)kg * 256 + ls;
            const float* r1 = r0 + 256;
            const uint32_t tbase = sb + (uint32_t)(mat * 4 + buf * 2 + half) * TILE_B;
            const int w = 4 * lj + ldd;
#pragma unroll
            for (int u = 0; u < 8; ++u) {
                const int c = ls + 16 * u;
                float fe = __ldg(r0 + 16 * u);
                float fo = __ldg(r1 + 16 * u);
                uint32_t hi, lo;
                asm("cvt.rn.bf16x2.f32 %0, %1, %2;" : "=r"(hi) : "f"(fo), "f"(fe));
                float feh = __int_as_float(hi << 16);
                float foh = __int_as_float(hi & 0xffff0000u);
                float fel = fe - feh, fol = fo - foh;
                asm("cvt.rn.bf16x2.f32 %0, %1, %2;" : "=r"(lo) : "f"(fol), "f"(fel));
                asm volatile("st.shared.v2.b32 [%0], {%1,%2};"
                             :: "r"(sw_addr(tbase, c, w)), "r"(hi), "r"(lo) : "memory");
            }
        }
    };

    // ---- compute one k16 sub-tile ----
    auto compute16 = [&](uint32_t AT, uint32_t BT) {
        uint32_t af[4][8];   // per m-tile: a0h,a0l,a2h,a2l, a1h,a1l,a3h,a3l
#pragma unroll
        for (int mi = 0; mi < 4; ++mi) {
            const int r = wm * 64 + mi * 16 + g;
            asm volatile("ld.shared.v4.b32 {%0,%1,%2,%3}, [%4];"
                : "=r"(af[mi][0]), "=r"(af[mi][1]), "=r"(af[mi][2]), "=r"(af[mi][3])
                : "r"(sw_addr(AT, r, 4 * tq)));
            asm volatile("ld.shared.v4.b32 {%0,%1,%2,%3}, [%4];"
                : "=r"(af[mi][4]), "=r"(af[mi][5]), "=r"(af[mi][6]), "=r"(af[mi][7])
                : "r"(sw_addr(AT, r + 8, 4 * tq)));
        }
        uint32_t bf[8][4];   // b0h, b0l, b1h, b1l
#pragma unroll
        for (int ni = 0; ni < 8; ++ni) {
            const int r = wn * 64 + ni * 8 + g;
            asm volatile("ld.shared.v4.b32 {%0,%1,%2,%3}, [%4];"
                : "=r"(bf[ni][0]), "=r"(bf[ni][1]), "=r"(bf[ni][2]), "=r"(bf[ni][3])
                : "r"(sw_addr(BT, r, 4 * tq)));
        }
#pragma unroll
        for (int mi = 0; mi < 4; ++mi)
#pragma unroll
            for (int ni = 0; ni < 8; ++ni) {
                // hi*hi
                MMA_BF16(acc[mi][ni], af[mi][0], af[mi][4], af[mi][2], af[mi][6],
                         bf[ni][0], bf[ni][2]);
                // hi*lo
                MMA_BF16(acc[mi][ni], af[mi][0], af[mi][4], af[mi][2], af[mi][6],
                         bf[ni][1], bf[ni][3]);
                // lo*hi
                MMA_BF16(acc[mi][ni], af[mi][1], af[mi][5], af[mi][3], af[mi][7],
                         bf[ni][0], bf[ni][2]);
            }
    };

    load_stage(0, 0);
    __syncthreads();

    for (int ks = 0; ks < NSTAGE; ++ks) {
        const int buf = ks & 1;
        const uint32_t A0 = sb + (uint32_t)(buf * 2 + 0) * TILE_B;
        const uint32_t A1 = sb + (uint32_t)(buf * 2 + 1) * TILE_B;
        const uint32_t B0 = sb + (uint32_t)(4 + buf * 2 + 0) * TILE_B;
        const uint32_t B1 = sb + (uint32_t)(4 + buf * 2 + 1) * TILE_B;
        compute16(A0, B0);
        compute16(A1, B1);
        if (ks + 1 < NSTAGE) load_stage(ks + 1, buf ^ 1);
        __syncthreads();
    }

    // ---- epilogue: add bias, store ----
#pragma unroll
    for (int ni = 0; ni < 8; ++ni) {
        const int oc = o0 + wn * 64 + ni * 8 + 2 * tq;
        const float2 bias = *(const float2*)(b1 + oc);
#pragma unroll
        for (int mi = 0; mi < 4; ++mi) {
            const int crow = c0 + wm * 64 + mi * 16 + g;
            float2 v0 = make_float2(acc[mi][ni][0] + bias.x, acc[mi][ni][1] + bias.y);
            float2 v1 = make_float2(acc[mi][ni][2] + bias.x, acc[mi][ni][3] + bias.y);
            *(float2*)(g_y + ((size_t)b * C2 + crow)     * OUTC + oc) = v0;
            *(float2*)(g_y + ((size_t)b * C2 + crow + 8) * OUTC + oc) = v1;
        }
    }
}

// ---------------- kernel 7: BN batch stats ---------------------------------------
__global__ __launch_bounds__(256) void stats_kernel() {
    const int c = blockIdx.x;
    const int o = threadIdx.x;
    float s = 0.f, s2 = 0.f;
#pragma unroll
    for (int b = 0; b < BB; ++b) {
        float v = g_y[((size_t)b * C2 + c) * OUTC + o];
        s += v;
        s2 = fmaf(v, v, s2);
    }
    __shared__ float rs[256], rq[256];
    rs[o] = s; rq[o] = s2;
    __syncthreads();
    for (int st = 128; st > 0; st >>= 1) {
        if (o < st) { rs[o] += rs[o + st]; rq[o] += rq[o + st]; }
        __syncthreads();
    }
    if (o == 0) {
        float mean = rs[0] * (1.f / 4096.f);
        float var  = rq[0] * (1.f / 4096.f) - mean * mean;
        g_mean[c] = mean;
        g_rstd[c] = rsqrtf(var + 1e-5f);
    }
}

// ---------------- kernel 8: BN apply + ReLU + transpose ---------------------------
__global__ void epilogue_kernel(const float* __restrict__ gamma,
                                const float* __restrict__ beta,
                                float* __restrict__ out) {
    __shared__ float tile[32][33];
    const int b = blockIdx.z, c0 = blockIdx.x * 32, o0 = blockIdx.y * 32;
    const int tx = threadIdx.x, ty = threadIdx.y;
#pragma unroll
    for (int i = 0; i < 4; ++i) {
        int c = c0 + ty + i * 8;
        float v = g_y[((size_t)b * C2 + c) * OUTC + o0 + tx];
        v = fmaf(gamma[c] * g_rstd[c], v - g_mean[c], beta[c]);
        tile[ty + i * 8][tx] = fmaxf(v, 0.f);
    }
    __syncthreads();
#pragma unroll
    for (int i = 0; i < 4; ++i) {
        int o = o0 + ty + i * 8;
        out[((size_t)b * OUTC + o) * C2 + c0 + tx] = tile[tx][ty + i * 8];
    }
}

// ---------------- launch -----------------------------------------------------------
extern "C" void kernel_launch(void* const* d_in, const int* in_sizes, int n_in,
                              void* d_out, int out_size) {
    const float* x2    = (const float*)d_in[1];
    const float* xyz1  = (const float*)d_in[2];
    const float* xyz2  = (const float*)d_in[3];
    const float* W1    = (const float*)d_in[4];
    const float* b1    = (const float*)d_in[5];
    const float* gamma = (const float*)d_in[6];
    const float* beta  = (const float*)d_in[7];
    float* out = (float*)d_out;

    const int dyn_smem = 8 * TILE_B;   // 64 KB
    cudaFuncSetAttribute(gemm_mma_kernel, cudaFuncAttributeMaxDynamicSharedMemorySize, dyn_smem);

    zero_kernel<<<(BB * N2 + 255) / 256, 256>>>();
    knn_kernel<<<dim3(N1 / 256, BB), 256>>>(xyz1, xyz2);
    scan_kernel<<<BB, 256>>>();
    fill_kernel<<<dim3(N1 / 256, BB), 256>>>();
    w1t_kernel<<<dim3(KG / 32, OUTC / 32), dim3(32, 8)>>>(W1);
    tbuild_kernel<<<dim3(N2, BB), 256>>>();
    gemm_mma_kernel<<<dim3(4, BB), 128, dyn_smem>>>(x2, b1);
    stats_kernel<<<C2, 256>>>();
    epilogue_kernel<<<dim3(8, 8, BB), dim3(32, 8)>>>(gamma, beta, out);
}

// round 5
// speedup vs baseline: 2.7227x; 1.1716x over previous
#include <cuda_runtime.h>
#include <cstdint>

#define BB   16
#define N1   4096
#define N2   1024
#define C2   256
#define OUTC 256
#define KG   4096
#define NNZ  (N1 * 3)

// ---------------- scratch ------------------------------------------------------
__device__ float4 g_wi[BB * N1];               // (w0,w1,w2, packed ids)
__device__ int   g_off[BB * N2];
__device__ int   g_end[BB * N2];
__device__ int   g_ln[BB * NNZ];
__device__ float g_lw[BB * NNZ];
__device__ float g_W1T[(size_t)KG * OUTC];
__device__ float g_T[(size_t)BB * N2 * OUTC];
__device__ float g_y[BB * C2 * OUTC];          // split-K partial 0 (+bias)
__device__ float g_y2[BB * C2 * OUTC];         // split-K partial 1
__device__ float g_mean[C2];
__device__ float g_rstd[C2];

__device__ __forceinline__ uint32_t smem_u32(const void* p) {
    uint32_t a;
    asm("{ .reg .u64 t; cvta.to.shared.u64 t, %1; cvt.u32.u64 %0, t; }" : "=r"(a) : "l"(p));
    return a;
}

// ---------------- kernel 0: 3-NN + weights (no atomics) -------------------------
__global__ __launch_bounds__(256) void knn_kernel(const float* __restrict__ xyz1,
                                                  const float* __restrict__ xyz2) {
    __shared__ float4 q[N2];
    const int b = blockIdx.y;
    const float* x2b = xyz2 + (size_t)b * N2 * 3;
    for (int j = threadIdx.x; j < N2; j += blockDim.x) {
        float x = x2b[j * 3 + 0], y = x2b[j * 3 + 1], z = x2b[j * 3 + 2];
        q[j] = make_float4(x, y, z, x * x + y * y + z * z);
    }
    __syncthreads();

    const int n = blockIdx.x * 256 + threadIdx.x;
    const float* p = xyz1 + ((size_t)b * N1 + n) * 3;
    const float px = p[0], py = p[1], pz = p[2];
    const float pp = px * px + py * py + pz * pz;
    const float ax = -2.f * px, ay = -2.f * py, az = -2.f * pz;

    const float INF = __int_as_float(0x7f800000);
    float s0 = INF, s1 = INF, s2 = INF;
    int i0 = 0, i1 = 0, i2 = 0;

#pragma unroll 8
    for (int j = 0; j < N2; ++j) {
        float4 Q = q[j];
        float s = fmaf(ax, Q.x, fmaf(ay, Q.y, fmaf(az, Q.z, Q.w)));
        if (s < s2) {
            if (s < s1) {
                s2 = s1; i2 = i1;
                if (s < s0) { s1 = s0; i1 = i0; s0 = s; i0 = j; }
                else        { s1 = s;  i1 = j; }
            } else { s2 = s; i2 = j; }
        }
    }
    float d0 = s0 + pp, d1 = s1 + pp, d2 = s2 + pp;
    float r0 = 1.f / (d0 + 1e-8f), r1 = 1.f / (d1 + 1e-8f), r2 = 1.f / (d2 + 1e-8f);
    float rs = 1.f / (r0 + r1 + r2);
    int packed = i0 | (i1 << 10) | (i2 << 20);
    g_wi[b * N1 + n] = make_float4(r0 * rs, r1 * rs, r2 * rs, __int_as_float(packed));
}

// ---------------- kernel 1: fused histogram + scan + CSC fill (per batch) -------
__global__ __launch_bounds__(1024) void scanfill_kernel() {
    __shared__ int hist[N2];
    __shared__ int sbuf[N2];
    __shared__ int cur[N2];
    const int b = blockIdx.x, t = threadIdx.x;
    hist[t] = 0;
    __syncthreads();
    const int base = b * N1;
#pragma unroll
    for (int n = t; n < N1; n += 1024) {
        int p = __float_as_int(g_wi[base + n].w);
        atomicAdd(&hist[p & 1023], 1);
        atomicAdd(&hist[(p >> 10) & 1023], 1);
        atomicAdd(&hist[(p >> 20) & 1023], 1);
    }
    __syncthreads();
    const int cnt = hist[t];
    sbuf[t] = cnt;
    __syncthreads();
    for (int st = 1; st < 1024; st <<= 1) {
        int a = (t >= st) ? sbuf[t - st] : 0;
        __syncthreads();
        sbuf[t] += a;
        __syncthreads();
    }
    const int excl = sbuf[t] - cnt;
    g_off[b * N2 + t] = excl;
    g_end[b * N2 + t] = excl + cnt;
    cur[t] = excl;
    __syncthreads();
    const int lbase = b * NNZ;
#pragma unroll
    for (int n = t; n < N1; n += 1024) {
        float4 wi = g_wi[base + n];
        int p = __float_as_int(wi.w);
        int i0 = p & 1023, i1 = (p >> 10) & 1023, i2 = (p >> 20) & 1023;
        int p0 = atomicAdd(&cur[i0], 1); g_ln[lbase + p0] = n; g_lw[lbase + p0] = wi.x;
        int p1 = atomicAdd(&cur[i1], 1); g_ln[lbase + p1] = n; g_lw[lbase + p1] = wi.y;
        int p2 = atomicAdd(&cur[i2], 1); g_ln[lbase + p2] = n; g_lw[lbase + p2] = wi.z;
    }
}

// ---------------- kernel 2: transpose W1 -> W1T ---------------------------------
__global__ void w1t_kernel(const float* __restrict__ W1) {
    __shared__ float tile[32][33];
    const int n0 = blockIdx.x * 32, o0 = blockIdx.y * 32;
    const int tx = threadIdx.x, ty = threadIdx.y;
#pragma unroll
    for (int i = 0; i < 4; ++i)
        tile[ty + i * 8][tx] = W1[(size_t)(o0 + ty + i * 8) * KG + n0 + tx];
    __syncthreads();
#pragma unroll
    for (int i = 0; i < 4; ++i)
        g_W1T[(size_t)(n0 + ty + i * 8) * OUTC + o0 + tx] = tile[tx][ty + i * 8];
}

// ---------------- kernel 3 (PROFILED SLOT): build T[b,m,o] ----------------------
// grid (N2/8, BB), block 256 (thread = o); 8 columns per block, no syncs.
__global__ __launch_bounds__(256) void tbuild_kernel() {
    const int b = blockIdx.y, m0 = blockIdx.x * 8, o = threadIdx.x;
    const int lbase = b * NNZ;
#pragma unroll
    for (int j = 0; j < 8; ++j) {
        const int m = m0 + j;
        const int s0 = __ldg(&g_off[b * N2 + m]);
        const int s1 = __ldg(&g_end[b * N2 + m]);
        float acc = 0.f;
        int i = s0;
        for (; i + 4 <= s1; i += 4) {
            int   n0 = __ldg(&g_ln[lbase + i]),     n1 = __ldg(&g_ln[lbase + i + 1]);
            int   n2 = __ldg(&g_ln[lbase + i + 2]), n3 = __ldg(&g_ln[lbase + i + 3]);
            float w0 = __ldg(&g_lw[lbase + i]),     w1 = __ldg(&g_lw[lbase + i + 1]);
            float w2 = __ldg(&g_lw[lbase + i + 2]), w3 = __ldg(&g_lw[lbase + i + 3]);
            float v0 = __ldg(&g_W1T[(size_t)n0 * OUTC + o]);
            float v1 = __ldg(&g_W1T[(size_t)n1 * OUTC + o]);
            float v2 = __ldg(&g_W1T[(size_t)n2 * OUTC + o]);
            float v3 = __ldg(&g_W1T[(size_t)n3 * OUTC + o]);
            acc = fmaf(w0, v0, acc); acc = fmaf(w1, v1, acc);
            acc = fmaf(w2, v2, acc); acc = fmaf(w3, v3, acc);
        }
        for (; i < s1; ++i) {
            int nn = __ldg(&g_ln[lbase + i]);
            float ww = __ldg(&g_lw[lbase + i]);
            acc = fmaf(ww, __ldg(&g_W1T[(size_t)nn * OUTC + o]), acc);
        }
        g_T[((size_t)b * N2 + m) * OUTC + o] = acc;
    }
}

// ---------------- kernel 4: mma.sync bf16 split-3 GEMM, split-K=2 ---------------
#define TILE_B 8192            // 128*16*4
#define NSTAGE 16              // 512 / 32 per split

#define MMA_BF16(d, A0, A1, A2, A3, B0, B1)                                     \
    asm volatile("mma.sync.aligned.m16n8k16.row.col.f32.bf16.bf16.f32 "         \
        "{%0,%1,%2,%3}, {%4,%5,%6,%7}, {%8,%9}, {%0,%1,%2,%3};"                 \
        : "+f"((d)[0]), "+f"((d)[1]), "+f"((d)[2]), "+f"((d)[3])                \
        : "r"(A0), "r"(A1), "r"(A2), "r"(A3), "r"(B0), "r"(B1))

__device__ __forceinline__ uint32_t sw_addr(uint32_t base, int row, int w) {
    return base + (uint32_t)(row * 16 + (w ^ ((row & 3) << 2))) * 4u;
}

__global__ __launch_bounds__(128, 1) void gemm_mma_kernel(const float* __restrict__ x2,
                                                          const float* __restrict__ b1) {
    extern __shared__ char dyn[];
    const uint32_t sb = smem_u32(dyn);

    const int b  = blockIdx.y;
    const int c0 = (blockIdx.x & 1) * 128;
    const int o0 = ((blockIdx.x >> 1) & 1) * 128;
    const int z  = blockIdx.x >> 2;
    const int kbase = z * 512;

    const int tid  = threadIdx.x;
    const int lane = tid & 31;
    const int wid  = tid >> 5;
    const int wm   = wid & 1;
    const int wn   = wid >> 1;
    const int g    = lane >> 2;
    const int tq   = lane & 3;

    const float* Ab = x2  + (size_t)b * N2 * C2   + c0;
    const float* Bb = g_T + (size_t)b * N2 * OUTC + o0;

    const int lp = tid >> 4;
    const int ls = tid & 15;
    const int lj = lp & 3;
    const int ldd = (lp >> 2) * 2;
    const int krow = 2 * lj + (lp >> 2) * 8;

    float acc[4][8][4];
#pragma unroll
    for (int mi = 0; mi < 4; ++mi)
#pragma unroll
        for (int ni = 0; ni < 8; ++ni)
#pragma unroll
            for (int r = 0; r < 4; ++r) acc[mi][ni][r] = 0.f;

    auto load_stage = [&](int ks, int buf) {
#pragma unroll
        for (int slot = 0; slot < 4; ++slot) {
            const int half = slot & 1, mat = slot >> 1;
            const float* src = mat ? Bb : Ab;
            const int kg = kbase + ks * 32 + half * 16 + krow;
            const float* r0 = src + (size_t)kg * 256 + ls;
            const float* r1 = r0 + 256;
            const uint32_t tbase = sb + (uint32_t)(mat * 4 + buf * 2 + half) * TILE_B;
            const int w = 4 * lj + ldd;
#pragma unroll
            for (int u = 0; u < 8; ++u) {
                const int c = ls + 16 * u;
                float fe = __ldg(r0 + 16 * u);
                float fo = __ldg(r1 + 16 * u);
                uint32_t hi, lo;
                asm("cvt.rn.bf16x2.f32 %0, %1, %2;" : "=r"(hi) : "f"(fo), "f"(fe));
                float feh = __int_as_float(hi << 16);
                float foh = __int_as_float(hi & 0xffff0000u);
                float fel = fe - feh, fol = fo - foh;
                asm("cvt.rn.bf16x2.f32 %0, %1, %2;" : "=r"(lo) : "f"(fol), "f"(fel));
                asm volatile("st.shared.v2.b32 [%0], {%1,%2};"
                             :: "r"(sw_addr(tbase, c, w)), "r"(hi), "r"(lo) : "memory");
            }
        }
    };

    auto compute16 = [&](uint32_t AT, uint32_t BT) {
        uint32_t af[4][8];
#pragma unroll
        for (int mi = 0; mi < 4; ++mi) {
            const int r = wm * 64 + mi * 16 + g;
            asm volatile("ld.shared.v4.b32 {%0,%1,%2,%3}, [%4];"
                : "=r"(af[mi][0]), "=r"(af[mi][1]), "=r"(af[mi][2]), "=r"(af[mi][3])
                : "r"(sw_addr(AT, r, 4 * tq)));
            asm volatile("ld.shared.v4.b32 {%0,%1,%2,%3}, [%4];"
                : "=r"(af[mi][4]), "=r"(af[mi][5]), "=r"(af[mi][6]), "=r"(af[mi][7])
                : "r"(sw_addr(AT, r + 8, 4 * tq)));
        }
        uint32_t bf[8][4];
#pragma unroll
        for (int ni = 0; ni < 8; ++ni) {
            const int r = wn * 64 + ni * 8 + g;
            asm volatile("ld.shared.v4.b32 {%0,%1,%2,%3}, [%4];"
                : "=r"(bf[ni][0]), "=r"(bf[ni][1]), "=r"(bf[ni][2]), "=r"(bf[ni][3])
                : "r"(sw_addr(BT, r, 4 * tq)));
        }
#pragma unroll
        for (int mi = 0; mi < 4; ++mi)
#pragma unroll
            for (int ni = 0; ni < 8; ++ni) {
                MMA_BF16(acc[mi][ni], af[mi][0], af[mi][4], af[mi][2], af[mi][6],
                         bf[ni][0], bf[ni][2]);
                MMA_BF16(acc[mi][ni], af[mi][0], af[mi][4], af[mi][2], af[mi][6],
                         bf[ni][1], bf[ni][3]);
                MMA_BF16(acc[mi][ni], af[mi][1], af[mi][5], af[mi][3], af[mi][7],
                         bf[ni][0], bf[ni][2]);
            }
    };

    load_stage(0, 0);
    __syncthreads();

    for (int ks = 0; ks < NSTAGE; ++ks) {
        const int buf = ks & 1;
        const uint32_t A0 = sb + (uint32_t)(buf * 2 + 0) * TILE_B;
        const uint32_t A1 = sb + (uint32_t)(buf * 2 + 1) * TILE_B;
        const uint32_t B0 = sb + (uint32_t)(4 + buf * 2 + 0) * TILE_B;
        const uint32_t B1 = sb + (uint32_t)(4 + buf * 2 + 1) * TILE_B;
        compute16(A0, B0);
        compute16(A1, B1);
        if (ks + 1 < NSTAGE) load_stage(ks + 1, buf ^ 1);
        __syncthreads();
    }

    float* Y = z ? g_y2 : g_y;
#pragma unroll
    for (int ni = 0; ni < 8; ++ni) {
        const int oc = o0 + wn * 64 + ni * 8 + 2 * tq;
        float2 bias = make_float2(0.f, 0.f);
        if (z == 0) bias = *(const float2*)(b1 + oc);
#pragma unroll
        for (int mi = 0; mi < 4; ++mi) {
            const int crow = c0 + wm * 64 + mi * 16 + g;
            float2 v0 = make_float2(acc[mi][ni][0] + bias.x, acc[mi][ni][1] + bias.y);
            float2 v1 = make_float2(acc[mi][ni][2] + bias.x, acc[mi][ni][3] + bias.y);
            *(float2*)(Y + ((size_t)b * C2 + crow)     * OUTC + oc) = v0;
            *(float2*)(Y + ((size_t)b * C2 + crow + 8) * OUTC + oc) = v1;
        }
    }
}

// ---------------- kernel 5: BN batch stats (reads both partials) ----------------
__global__ __launch_bounds__(256) void stats_kernel() {
    const int c = blockIdx.x;
    const int o = threadIdx.x;
    float s = 0.f, s2 = 0.f;
#pragma unroll
    for (int b = 0; b < BB; ++b) {
        size_t idx = ((size_t)b * C2 + c) * OUTC + o;
        float v = g_y[idx] + g_y2[idx];
        s += v;
        s2 = fmaf(v, v, s2);
    }
    __shared__ float rs[256], rq[256];
    rs[o] = s; rq[o] = s2;
    __syncthreads();
    for (int st = 128; st > 0; st >>= 1) {
        if (o < st) { rs[o] += rs[o + st]; rq[o] += rq[o + st]; }
        __syncthreads();
    }
    if (o == 0) {
        float mean = rs[0] * (1.f / 4096.f);
        float var  = rq[0] * (1.f / 4096.f) - mean * mean;
        g_mean[c] = mean;
        g_rstd[c] = rsqrtf(var + 1e-5f);
    }
}

// ---------------- kernel 6: BN apply + ReLU + transpose -------------------------
__global__ void epilogue_kernel(const float* __restrict__ gamma,
                                const float* __restrict__ beta,
                                float* __restrict__ out) {
    __shared__ float tile[32][33];
    const int b = blockIdx.z, c0 = blockIdx.x * 32, o0 = blockIdx.y * 32;
    const int tx = threadIdx.x, ty = threadIdx.y;
#pragma unroll
    for (int i = 0; i < 4; ++i) {
        int c = c0 + ty + i * 8;
        size_t idx = ((size_t)b * C2 + c) * OUTC + o0 + tx;
        float v = g_y[idx] + g_y2[idx];
        v = fmaf(gamma[c] * g_rstd[c], v - g_mean[c], beta[c]);
        tile[ty + i * 8][tx] = fmaxf(v, 0.f);
    }
    __syncthreads();
#pragma unroll
    for (int i = 0; i < 4; ++i) {
        int o = o0 + ty + i * 8;
        out[((size_t)b * OUTC + o) * C2 + c0 + tx] = tile[tx][ty + i * 8];
    }
}

// ---------------- launch ----------------------------------------------------------
extern "C" void kernel_launch(void* const* d_in, const int* in_sizes, int n_in,
                              void* d_out, int out_size) {
    const float* x2    = (const float*)d_in[1];
    const float* xyz1  = (const float*)d_in[2];
    const float* xyz2  = (const float*)d_in[3];
    const float* W1    = (const float*)d_in[4];
    const float* b1    = (const float*)d_in[5];
    const float* gamma = (const float*)d_in[6];
    const float* beta  = (const float*)d_in[7];
    float* out = (float*)d_out;

    const int dyn_smem = 8 * TILE_B;   // 64 KB
    cudaFuncSetAttribute(gemm_mma_kernel, cudaFuncAttributeMaxDynamicSharedMemorySize, dyn_smem);

    knn_kernel<<<dim3(N1 / 256, BB), 256>>>(xyz1, xyz2);        // idx 0
    scanfill_kernel<<<BB, 1024>>>();                            // idx 1
    w1t_kernel<<<dim3(KG / 32, OUTC / 32), dim3(32, 8)>>>(W1);  // idx 2
    tbuild_kernel<<<dim3(N2 / 8, BB), 256>>>();                 // idx 3  <- profiled
    gemm_mma_kernel<<<dim3(8, BB), 128, dyn_smem>>>(x2, b1);    // idx 4
    stats_kernel<<<C2, 256>>>();                                // idx 5
    epilogue_kernel<<<dim3(8, 8, BB), dim3(32, 8)>>>(gamma, beta, out); // idx 6
}

// round 6
// speedup vs baseline: 3.3032x; 1.2132x over previous
#include <cuda_runtime.h>
#include <cstdint>

#define BB   16
#define N1   4096
#define N2   1024
#define C2   256
#define OUTC 256
#define KG   4096
#define NNZ  (N1 * 3)

// ---------------- scratch ------------------------------------------------------
__device__ float4 g_wi[BB * N1];               // (w0,w1,w2, packed ids)
__device__ int    g_off[BB * N2];
__device__ int    g_end[BB * N2];
__device__ float2 g_le[BB * NNZ];              // (weight, n as int bits)
__device__ float  g_W1T[(size_t)KG * OUTC];
__device__ float  g_T[(size_t)BB * N2 * OUTC];
__device__ float  g_y[BB * C2 * OUTC];         // split-K partial 0 (+bias)
__device__ float  g_y2[BB * C2 * OUTC];        // split-K partial 1
__device__ float  g_mean[C2];
__device__ float  g_rstd[C2];

__device__ __forceinline__ uint32_t smem_u32(const void* p) {
    uint32_t a;
    asm("{ .reg .u64 t; cvta.to.shared.u64 t, %1; cvt.u32.u64 %0, t; }" : "=r"(a) : "l"(p));
    return a;
}

// ---------------- kernel 0: 3-NN + weights (no atomics) -------------------------
__global__ __launch_bounds__(256) void knn_kernel(const float* __restrict__ xyz1,
                                                  const float* __restrict__ xyz2) {
    __shared__ float4 q[N2];
    const int b = blockIdx.y;
    const float* x2b = xyz2 + (size_t)b * N2 * 3;
    for (int j = threadIdx.x; j < N2; j += blockDim.x) {
        float x = x2b[j * 3 + 0], y = x2b[j * 3 + 1], z = x2b[j * 3 + 2];
        q[j] = make_float4(x, y, z, x * x + y * y + z * z);
    }
    __syncthreads();

    const int n = blockIdx.x * 256 + threadIdx.x;
    const float* p = xyz1 + ((size_t)b * N1 + n) * 3;
    const float px = p[0], py = p[1], pz = p[2];
    const float pp = px * px + py * py + pz * pz;
    const float ax = -2.f * px, ay = -2.f * py, az = -2.f * pz;

    const float INF = __int_as_float(0x7f800000);
    float s0 = INF, s1 = INF, s2 = INF;
    int i0 = 0, i1 = 0, i2 = 0;

#pragma unroll 8
    for (int j = 0; j < N2; ++j) {
        float4 Q = q[j];
        float s = fmaf(ax, Q.x, fmaf(ay, Q.y, fmaf(az, Q.z, Q.w)));
        if (s < s2) {
            if (s < s1) {
                s2 = s1; i2 = i1;
                if (s < s0) { s1 = s0; i1 = i0; s0 = s; i0 = j; }
                else        { s1 = s;  i1 = j; }
            } else { s2 = s; i2 = j; }
        }
    }
    float d0 = s0 + pp, d1 = s1 + pp, d2 = s2 + pp;
    float r0 = 1.f / (d0 + 1e-8f), r1 = 1.f / (d1 + 1e-8f), r2 = 1.f / (d2 + 1e-8f);
    float rs = 1.f / (r0 + r1 + r2);
    int packed = i0 | (i1 << 10) | (i2 << 20);
    g_wi[b * N1 + n] = make_float4(r0 * rs, r1 * rs, r2 * rs, __int_as_float(packed));
}

// ---------------- kernel 1: fused (scan+fill) | (W1 transpose) ------------------
// blocks [0,BB): per-batch histogram + warp-shuffle scan + CSC fill
// blocks [BB, BB+256): 64x64 transpose tiles of W1 -> W1T
__global__ __launch_bounds__(1024) void prep_kernel(const float* __restrict__ W1) {
    __shared__ __align__(16) char smem[66560];   // max(8KB+128, 64*65*4)
    const int t = threadIdx.x;

    if (blockIdx.x < BB) {
        int* hist  = (int*)smem;                 // 1024 ints
        int* cur   = hist + N2;                  // 1024 ints
        int* wpart = cur + N2;                   // 32 ints
        const int b = blockIdx.x;
        hist[t] = 0;
        __syncthreads();
        const int base = b * N1;
        for (int n = t; n < N1; n += 1024) {
            int p = __float_as_int(g_wi[base + n].w);
            atomicAdd(&hist[p & 1023], 1);
            atomicAdd(&hist[(p >> 10) & 1023], 1);
            atomicAdd(&hist[(p >> 20) & 1023], 1);
        }
        __syncthreads();
        const int cnt = hist[t];
        const int lane = t & 31, wid = t >> 5;
        int v = cnt;
#pragma unroll
        for (int d = 1; d < 32; d <<= 1) {
            int u = __shfl_up_sync(0xffffffffu, v, d);
            if (lane >= d) v += u;
        }
        if (lane == 31) wpart[wid] = v;
        __syncthreads();
        if (wid == 0) {
            int w = wpart[lane];
#pragma unroll
            for (int d = 1; d < 32; d <<= 1) {
                int u = __shfl_up_sync(0xffffffffu, w, d);
                if (lane >= d) w += u;
            }
            wpart[lane] = w;
        }
        __syncthreads();
        const int excl = v - cnt + (wid > 0 ? wpart[wid - 1] : 0);
        g_off[b * N2 + t] = excl;
        g_end[b * N2 + t] = excl + cnt;
        cur[t] = excl;
        __syncthreads();
        const int lbase = b * NNZ;
        for (int n = t; n < N1; n += 1024) {
            float4 wi = g_wi[base + n];
            int p = __float_as_int(wi.w);
            float fn = __int_as_float(n);
            int p0 = atomicAdd(&cur[p & 1023], 1);
            g_le[lbase + p0] = make_float2(wi.x, fn);
            int p1 = atomicAdd(&cur[(p >> 10) & 1023], 1);
            g_le[lbase + p1] = make_float2(wi.y, fn);
            int p2 = atomicAdd(&cur[(p >> 20) & 1023], 1);
            g_le[lbase + p2] = make_float2(wi.z, fn);
        }
    } else {
        float (*tile)[65] = (float (*)[65])smem;
        const int tt = blockIdx.x - BB;          // 0..255
        const int n0 = (tt & 63) * 64, o0 = (tt >> 6) * 64;
        const int tx = t & 63, ty = t >> 6;      // 16 rows per pass
#pragma unroll
        for (int i = 0; i < 4; ++i)
            tile[ty + 16 * i][tx] = W1[(size_t)(o0 + ty + 16 * i) * KG + n0 + tx];
        __syncthreads();
#pragma unroll
        for (int i = 0; i < 4; ++i)
            g_W1T[(size_t)(n0 + ty + 16 * i) * OUTC + o0 + tx] = tile[tx][ty + 16 * i];
    }
}

// ---------------- kernel 2: build T[b,m,o] (float4, 4 m per block) --------------
__global__ __launch_bounds__(256) void tbuild_kernel() {
    const int b = blockIdx.y;
    const int m = blockIdx.x * 4 + (threadIdx.x >> 6);
    const int o4 = (threadIdx.x & 63) << 2;
    const int lbase = b * NNZ;
    const int s0 = __ldg(&g_off[b * N2 + m]);
    const int s1 = __ldg(&g_end[b * N2 + m]);

    float4 acc = make_float4(0.f, 0.f, 0.f, 0.f);
    int i = s0;
    for (; i + 2 <= s1; i += 2) {
        float2 e0 = __ldg(&g_le[lbase + i]);
        float2 e1 = __ldg(&g_le[lbase + i + 1]);
        int n0 = __float_as_int(e0.y), n1 = __float_as_int(e1.y);
        float4 v0 = *(const float4*)(g_W1T + ((size_t)n0 << 8) + o4);
        float4 v1 = *(const float4*)(g_W1T + ((size_t)n1 << 8) + o4);
        acc.x = fmaf(e0.x, v0.x, acc.x); acc.y = fmaf(e0.x, v0.y, acc.y);
        acc.z = fmaf(e0.x, v0.z, acc.z); acc.w = fmaf(e0.x, v0.w, acc.w);
        acc.x = fmaf(e1.x, v1.x, acc.x); acc.y = fmaf(e1.x, v1.y, acc.y);
        acc.z = fmaf(e1.x, v1.z, acc.z); acc.w = fmaf(e1.x, v1.w, acc.w);
    }
    if (i < s1) {
        float2 e = __ldg(&g_le[lbase + i]);
        int n = __float_as_int(e.y);
        float4 v = *(const float4*)(g_W1T + ((size_t)n << 8) + o4);
        acc.x = fmaf(e.x, v.x, acc.x); acc.y = fmaf(e.x, v.y, acc.y);
        acc.z = fmaf(e.x, v.z, acc.z); acc.w = fmaf(e.x, v.w, acc.w);
    }
    *(float4*)(g_T + ((size_t)b * N2 + m) * OUTC + o4) = acc;
}

// ---------------- kernel 3 (PROFILED): mma.sync bf16 split-3 GEMM, split-K=2 ----
#define TILE_B 8192            // 128*16*4
#define NSTAGE 16              // 512 / 32 per split

#define MMA_BF16(d, A0, A1, A2, A3, B0, B1)                                     \
    asm volatile("mma.sync.aligned.m16n8k16.row.col.f32.bf16.bf16.f32 "         \
        "{%0,%1,%2,%3}, {%4,%5,%6,%7}, {%8,%9}, {%0,%1,%2,%3};"                 \
        : "+f"((d)[0]), "+f"((d)[1]), "+f"((d)[2]), "+f"((d)[3])                \
        : "r"(A0), "r"(A1), "r"(A2), "r"(A3), "r"(B0), "r"(B1))

__device__ __forceinline__ uint32_t sw_addr(uint32_t base, int row, int w) {
    return base + (uint32_t)(row * 16 + (w ^ ((row & 3) << 2))) * 4u;
}

__global__ __launch_bounds__(128, 1) void gemm_mma_kernel(const float* __restrict__ x2,
                                                          const float* __restrict__ b1) {
    extern __shared__ char dyn[];
    const uint32_t sb = smem_u32(dyn);

    const int b  = blockIdx.y;
    const int c0 = (blockIdx.x & 1) * 128;
    const int o0 = ((blockIdx.x >> 1) & 1) * 128;
    const int z  = blockIdx.x >> 2;
    const int kbase = z * 512;

    const int tid  = threadIdx.x;
    const int lane = tid & 31;
    const int wid  = tid >> 5;
    const int wm   = wid & 1;
    const int wn   = wid >> 1;
    const int g    = lane >> 2;
    const int tq   = lane & 3;

    const float* Ab = x2  + (size_t)b * N2 * C2   + c0;
    const float* Bb = g_T + (size_t)b * N2 * OUTC + o0;

    const int lp = tid >> 4;
    const int ls = tid & 15;
    const int lj = lp & 3;
    const int ldd = (lp >> 2) * 2;
    const int krow = 2 * lj + (lp >> 2) * 8;

    float acc[4][8][4];
#pragma unroll
    for (int mi = 0; mi < 4; ++mi)
#pragma unroll
        for (int ni = 0; ni < 8; ++ni)
#pragma unroll
            for (int r = 0; r < 4; ++r) acc[mi][ni][r] = 0.f;

    auto load_stage = [&](int ks, int buf) {
#pragma unroll
        for (int slot = 0; slot < 4; ++slot) {
            const int half = slot & 1, mat = slot >> 1;
            const float* src = mat ? Bb : Ab;
            const int kg = kbase + ks * 32 + half * 16 + krow;
            const float* r0 = src + (size_t)kg * 256 + ls;
            const float* r1 = r0 + 256;
            const uint32_t tbase = sb + (uint32_t)(mat * 4 + buf * 2 + half) * TILE_B;
            const int w = 4 * lj + ldd;
#pragma unroll
            for (int u = 0; u < 8; ++u) {
                const int c = ls + 16 * u;
                float fe = __ldg(r0 + 16 * u);
                float fo = __ldg(r1 + 16 * u);
                uint32_t hi, lo;
                asm("cvt.rn.bf16x2.f32 %0, %1, %2;" : "=r"(hi) : "f"(fo), "f"(fe));
                float feh = __int_as_float(hi << 16);
                float foh = __int_as_float(hi & 0xffff0000u);
                float fel = fe - feh, fol = fo - foh;
                asm("cvt.rn.bf16x2.f32 %0, %1, %2;" : "=r"(lo) : "f"(fol), "f"(fel));
                asm volatile("st.shared.v2.b32 [%0], {%1,%2};"
                             :: "r"(sw_addr(tbase, c, w)), "r"(hi), "r"(lo) : "memory");
            }
        }
    };

    auto compute16 = [&](uint32_t AT, uint32_t BT) {
        uint32_t af[4][8];
#pragma unroll
        for (int mi = 0; mi < 4; ++mi) {
            const int r = wm * 64 + mi * 16 + g;
            asm volatile("ld.shared.v4.b32 {%0,%1,%2,%3}, [%4];"
                : "=r"(af[mi][0]), "=r"(af[mi][1]), "=r"(af[mi][2]), "=r"(af[mi][3])
                : "r"(sw_addr(AT, r, 4 * tq)));
            asm volatile("ld.shared.v4.b32 {%0,%1,%2,%3}, [%4];"
                : "=r"(af[mi][4]), "=r"(af[mi][5]), "=r"(af[mi][6]), "=r"(af[mi][7])
                : "r"(sw_addr(AT, r + 8, 4 * tq)));
        }
        uint32_t bf[8][4];
#pragma unroll
        for (int ni = 0; ni < 8; ++ni) {
            const int r = wn * 64 + ni * 8 + g;
            asm volatile("ld.shared.v4.b32 {%0,%1,%2,%3}, [%4];"
                : "=r"(bf[ni][0]), "=r"(bf[ni][1]), "=r"(bf[ni][2]), "=r"(bf[ni][3])
                : "r"(sw_addr(BT, r, 4 * tq)));
        }
#pragma unroll
        for (int mi = 0; mi < 4; ++mi)
#pragma unroll
            for (int ni = 0; ni < 8; ++ni) {
                MMA_BF16(acc[mi][ni], af[mi][0], af[mi][4], af[mi][2], af[mi][6],
                         bf[ni][0], bf[ni][2]);
                MMA_BF16(acc[mi][ni], af[mi][0], af[mi][4], af[mi][2], af[mi][6],
                         bf[ni][1], bf[ni][3]);
                MMA_BF16(acc[mi][ni], af[mi][1], af[mi][5], af[mi][3], af[mi][7],
                         bf[ni][0], bf[ni][2]);
            }
    };

    load_stage(0, 0);
    __syncthreads();

    for (int ks = 0; ks < NSTAGE; ++ks) {
        const int buf = ks & 1;
        const uint32_t A0 = sb + (uint32_t)(buf * 2 + 0) * TILE_B;
        const uint32_t A1 = sb + (uint32_t)(buf * 2 + 1) * TILE_B;
        const uint32_t B0 = sb + (uint32_t)(4 + buf * 2 + 0) * TILE_B;
        const uint32_t B1 = sb + (uint32_t)(4 + buf * 2 + 1) * TILE_B;
        compute16(A0, B0);
        compute16(A1, B1);
        if (ks + 1 < NSTAGE) load_stage(ks + 1, buf ^ 1);
        __syncthreads();
    }

    float* Y = z ? g_y2 : g_y;
#pragma unroll
    for (int ni = 0; ni < 8; ++ni) {
        const int oc = o0 + wn * 64 + ni * 8 + 2 * tq;
        float2 bias = make_float2(0.f, 0.f);
        if (z == 0) bias = *(const float2*)(b1 + oc);
#pragma unroll
        for (int mi = 0; mi < 4; ++mi) {
            const int crow = c0 + wm * 64 + mi * 16 + g;
            float2 v0 = make_float2(acc[mi][ni][0] + bias.x, acc[mi][ni][1] + bias.y);
            float2 v1 = make_float2(acc[mi][ni][2] + bias.x, acc[mi][ni][3] + bias.y);
            *(float2*)(Y + ((size_t)b * C2 + crow)     * OUTC + oc) = v0;
            *(float2*)(Y + ((size_t)b * C2 + crow + 8) * OUTC + oc) = v1;
        }
    }
}

// ---------------- kernel 4: BN batch stats (reads both partials) ----------------
__global__ __launch_bounds__(256) void stats_kernel() {
    const int c = blockIdx.x;
    const int o = threadIdx.x;
    float s = 0.f, s2 = 0.f;
#pragma unroll
    for (int b = 0; b < BB; ++b) {
        size_t idx = ((size_t)b * C2 + c) * OUTC + o;
        float v = g_y[idx] + g_y2[idx];
        s += v;
        s2 = fmaf(v, v, s2);
    }
    __shared__ float rs[256], rq[256];
    rs[o] = s; rq[o] = s2;
    __syncthreads();
    for (int st = 128; st > 0; st >>= 1) {
        if (o < st) { rs[o] += rs[o + st]; rq[o] += rq[o + st]; }
        __syncthreads();
    }
    if (o == 0) {
        float mean = rs[0] * (1.f / 4096.f);
        float var  = rq[0] * (1.f / 4096.f) - mean * mean;
        g_mean[c] = mean;
        g_rstd[c] = rsqrtf(var + 1e-5f);
    }
}

// ---------------- kernel 5: BN apply + ReLU + transpose -------------------------
__global__ void epilogue_kernel(const float* __restrict__ gamma,
                                const float* __restrict__ beta,
                                float* __restrict__ out) {
    __shared__ float tile[32][33];
    const int b = blockIdx.z, c0 = blockIdx.x * 32, o0 = blockIdx.y * 32;
    const int tx = threadIdx.x, ty = threadIdx.y;
#pragma unroll
    for (int i = 0; i < 4; ++i) {
        int c = c0 + ty + i * 8;
        size_t idx = ((size_t)b * C2 + c) * OUTC + o0 + tx;
        float v = g_y[idx] + g_y2[idx];
        v = fmaf(gamma[c] * g_rstd[c], v - g_mean[c], beta[c]);
        tile[ty + i * 8][tx] = fmaxf(v, 0.f);
    }
    __syncthreads();
#pragma unroll
    for (int i = 0; i < 4; ++i) {
        int o = o0 + ty + i * 8;
        out[((size_t)b * OUTC + o) * C2 + c0 + tx] = tile[tx][ty + i * 8];
    }
}

// ---------------- launch ----------------------------------------------------------
extern "C" void kernel_launch(void* const* d_in, const int* in_sizes, int n_in,
                              void* d_out, int out_size) {
    const float* x2    = (const float*)d_in[1];
    const float* xyz1  = (const float*)d_in[2];
    const float* xyz2  = (const float*)d_in[3];
    const float* W1    = (const float*)d_in[4];
    const float* b1    = (const float*)d_in[5];
    const float* gamma = (const float*)d_in[6];
    const float* beta  = (const float*)d_in[7];
    float* out = (float*)d_out;

    const int dyn_smem = 8 * TILE_B;   // 64 KB
    cudaFuncSetAttribute(gemm_mma_kernel, cudaFuncAttributeMaxDynamicSharedMemorySize, dyn_smem);

    knn_kernel<<<dim3(N1 / 256, BB), 256>>>(xyz1, xyz2);        // idx 0
    prep_kernel<<<BB + 256, 1024>>>(W1);                        // idx 1
    tbuild_kernel<<<dim3(N2 / 4, BB), 256>>>();                 // idx 2
    gemm_mma_kernel<<<dim3(8, BB), 128, dyn_smem>>>(x2, b1);    // idx 3  <- profiled
    stats_kernel<<<C2, 256>>>();                                // idx 4
    epilogue_kernel<<<dim3(8, 8, BB), dim3(32, 8)>>>(gamma, beta, out); // idx 5
}

// round 7
// speedup vs baseline: 3.5419x; 1.0723x over previous
#include <cuda_runtime.h>
#include <cstdint>

#define BB   16
#define N1   4096
#define N2   1024
#define C2   256
#define OUTC 256
#define KG   4096
#define NNZ  (N1 * 3)

// ---------------- scratch ------------------------------------------------------
__device__ float4   g_wi[BB * N1];
__device__ int      g_off[BB * N2];
__device__ int      g_end[BB * N2];
__device__ float2   g_le[BB * NNZ];
__device__ float    g_W1T[(size_t)KG * OUTC];
__device__ float    g_T[(size_t)BB * N2 * OUTC];
__device__ uint32_t g_AP[(size_t)BB * C2 * N2];    // packed bf16 (hi<<16|lo), [b][c][k]
__device__ uint32_t g_BP[(size_t)BB * OUTC * N2];  // packed bf16, [b][o][k]
__device__ float    g_y[BB * C2 * OUTC];
__device__ float    g_y2[BB * C2 * OUTC];
__device__ float    g_mean[C2];
__device__ float    g_rstd[C2];

__device__ __forceinline__ uint32_t smem_u32(const void* p) {
    uint32_t a;
    asm("{ .reg .u64 t; cvta.to.shared.u64 t, %1; cvt.u32.u64 %0, t; }" : "=r"(a) : "l"(p));
    return a;
}

// ---------------- kernel: pack fp32 [b][1024][256] -> bf16-split [b][256][1024] --
__global__ __launch_bounds__(256) void conv_kernel(const float* __restrict__ src,
                                                   uint32_t* __restrict__ dst) {
    __shared__ float t[32][33];
    const int b = blockIdx.z;
    const int k0 = blockIdx.x * 32, c0 = blockIdx.y * 32;
    const int tx = threadIdx.x, ty = threadIdx.y;
#pragma unroll
    for (int i = 0; i < 4; ++i)
        t[ty + 8 * i][tx] = src[((size_t)(b * N2 + k0 + ty + 8 * i)) * 256 + c0 + tx];
    __syncthreads();
#pragma unroll
    for (int i = 0; i < 4; ++i) {
        float f = t[tx][ty + 8 * i];
        uint32_t hh, p;
        asm("cvt.rn.bf16x2.f32 %0, %1, %2;" : "=r"(hh) : "f"(f), "f"(f));
        float fh = __int_as_float(hh & 0xffff0000u);
        float fl = f - fh;
        asm("cvt.rn.bf16x2.f32 %0, %1, %2;" : "=r"(p) : "f"(f), "f"(fl));
        dst[((size_t)(b * 256 + c0 + ty + 8 * i)) * N2 + k0 + tx] = p;
    }
}

// ---------------- kernel: 3-NN + weights ----------------------------------------
__global__ __launch_bounds__(256) void knn_kernel(const float* __restrict__ xyz1,
                                                  const float* __restrict__ xyz2) {
    __shared__ float4 q[N2];
    const int b = blockIdx.y;
    const float* x2b = xyz2 + (size_t)b * N2 * 3;
    for (int j = threadIdx.x; j < N2; j += blockDim.x) {
        float x = x2b[j * 3 + 0], y = x2b[j * 3 + 1], z = x2b[j * 3 + 2];
        q[j] = make_float4(x, y, z, x * x + y * y + z * z);
    }
    __syncthreads();

    const int n = blockIdx.x * 256 + threadIdx.x;
    const float* p = xyz1 + ((size_t)b * N1 + n) * 3;
    const float px = p[0], py = p[1], pz = p[2];
    const float pp = px * px + py * py + pz * pz;
    const float ax = -2.f * px, ay = -2.f * py, az = -2.f * pz;

    const float INF = __int_as_float(0x7f800000);
    float s0 = INF, s1 = INF, s2 = INF;
    int i0 = 0, i1 = 0, i2 = 0;

#pragma unroll 8
    for (int j = 0; j < N2; ++j) {
        float4 Q = q[j];
        float s = fmaf(ax, Q.x, fmaf(ay, Q.y, fmaf(az, Q.z, Q.w)));
        if (s < s2) {
            if (s < s1) {
                s2 = s1; i2 = i1;
                if (s < s0) { s1 = s0; i1 = i0; s0 = s; i0 = j; }
                else        { s1 = s;  i1 = j; }
            } else { s2 = s; i2 = j; }
        }
    }
    float d0 = s0 + pp, d1 = s1 + pp, d2 = s2 + pp;
    float r0 = 1.f / (d0 + 1e-8f), r1 = 1.f / (d1 + 1e-8f), r2 = 1.f / (d2 + 1e-8f);
    float rs = 1.f / (r0 + r1 + r2);
    int packed = i0 | (i1 << 10) | (i2 << 20);
    g_wi[b * N1 + n] = make_float4(r0 * rs, r1 * rs, r2 * rs, __int_as_float(packed));
}

// ---------------- kernel: fused (scan+fill) | (W1 transpose) --------------------
__global__ __launch_bounds__(1024) void prep_kernel(const float* __restrict__ W1) {
    __shared__ __align__(16) char smem[66560];
    const int t = threadIdx.x;

    if (blockIdx.x < BB) {
        int* hist  = (int*)smem;
        int* cur   = hist + N2;
        int* wpart = cur + N2;
        const int b = blockIdx.x;
        hist[t] = 0;
        __syncthreads();
        const int base = b * N1;
        for (int n = t; n < N1; n += 1024) {
            int p = __float_as_int(g_wi[base + n].w);
            atomicAdd(&hist[p & 1023], 1);
            atomicAdd(&hist[(p >> 10) & 1023], 1);
            atomicAdd(&hist[(p >> 20) & 1023], 1);
        }
        __syncthreads();
        const int cnt = hist[t];
        const int lane = t & 31, wid = t >> 5;
        int v = cnt;
#pragma unroll
        for (int d = 1; d < 32; d <<= 1) {
            int u = __shfl_up_sync(0xffffffffu, v, d);
            if (lane >= d) v += u;
        }
        if (lane == 31) wpart[wid] = v;
        __syncthreads();
        if (wid == 0) {
            int w = wpart[lane];
#pragma unroll
            for (int d = 1; d < 32; d <<= 1) {
                int u = __shfl_up_sync(0xffffffffu, w, d);
                if (lane >= d) w += u;
            }
            wpart[lane] = w;
        }
        __syncthreads();
        const int excl = v - cnt + (wid > 0 ? wpart[wid - 1] : 0);
        g_off[b * N2 + t] = excl;
        g_end[b * N2 + t] = excl + cnt;
        cur[t] = excl;
        __syncthreads();
        const int lbase = b * NNZ;
        for (int n = t; n < N1; n += 1024) {
            float4 wi = g_wi[base + n];
            int p = __float_as_int(wi.w);
            float fn = __int_as_float(n);
            int p0 = atomicAdd(&cur[p & 1023], 1);
            g_le[lbase + p0] = make_float2(wi.x, fn);
            int p1 = atomicAdd(&cur[(p >> 10) & 1023], 1);
            g_le[lbase + p1] = make_float2(wi.y, fn);
            int p2 = atomicAdd(&cur[(p >> 20) & 1023], 1);
            g_le[lbase + p2] = make_float2(wi.z, fn);
        }
    } else {
        float (*tile)[65] = (float (*)[65])smem;
        const int tt = blockIdx.x - BB;
        const int n0 = (tt & 63) * 64, o0 = (tt >> 6) * 64;
        const int tx = t & 63, ty = t >> 6;
#pragma unroll
        for (int i = 0; i < 4; ++i)
            tile[ty + 16 * i][tx] = W1[(size_t)(o0 + ty + 16 * i) * KG + n0 + tx];
        __syncthreads();
#pragma unroll
        for (int i = 0; i < 4; ++i)
            g_W1T[(size_t)(n0 + ty + 16 * i) * OUTC + o0 + tx] = tile[tx][ty + 16 * i];
    }
}

// ---------------- kernel (PROFILED): build T[b,m,o] (float4, 4 m per block) -----
__global__ __launch_bounds__(256) void tbuild_kernel() {
    const int b = blockIdx.y;
    const int m = blockIdx.x * 4 + (threadIdx.x >> 6);
    const int o4 = (threadIdx.x & 63) << 2;
    const int lbase = b * NNZ;
    const int s0 = __ldg(&g_off[b * N2 + m]);
    const int s1 = __ldg(&g_end[b * N2 + m]);

    float4 acc = make_float4(0.f, 0.f, 0.f, 0.f);
    int i = s0;
    for (; i + 2 <= s1; i += 2) {
        float2 e0 = __ldg(&g_le[lbase + i]);
        float2 e1 = __ldg(&g_le[lbase + i + 1]);
        int n0 = __float_as_int(e0.y), n1 = __float_as_int(e1.y);
        float4 v0 = *(const float4*)(g_W1T + ((size_t)n0 << 8) + o4);
        float4 v1 = *(const float4*)(g_W1T + ((size_t)n1 << 8) + o4);
        acc.x = fmaf(e0.x, v0.x, acc.x); acc.y = fmaf(e0.x, v0.y, acc.y);
        acc.z = fmaf(e0.x, v0.z, acc.z); acc.w = fmaf(e0.x, v0.w, acc.w);
        acc.x = fmaf(e1.x, v1.x, acc.x); acc.y = fmaf(e1.x, v1.y, acc.y);
        acc.z = fmaf(e1.x, v1.z, acc.z); acc.w = fmaf(e1.x, v1.w, acc.w);
    }
    if (i < s1) {
        float2 e = __ldg(&g_le[lbase + i]);
        int n = __float_as_int(e.y);
        float4 v = *(const float4*)(g_W1T + ((size_t)n << 8) + o4);
        acc.x = fmaf(e.x, v.x, acc.x); acc.y = fmaf(e.x, v.y, acc.y);
        acc.z = fmaf(e.x, v.z, acc.z); acc.w = fmaf(e.x, v.w, acc.w);
    }
    *(float4*)(g_T + ((size_t)b * N2 + m) * OUTC + o4) = acc;
}

// ---------------- GEMM: mma.sync bf16 split-3, ldmatrix, 8 warps ---------------
#define GTILE 8192             // one 128row x 32k bf16 tile
#define NSTAGE 16              // 512 / 32 per split

#define MMA_BF16(d, A0, A1, A2, A3, B0, B1)                                     \
    asm volatile("mma.sync.aligned.m16n8k16.row.col.f32.bf16.bf16.f32 "         \
        "{%0,%1,%2,%3}, {%4,%5,%6,%7}, {%8,%9}, {%0,%1,%2,%3};"                 \
        : "+f"((d)[0]), "+f"((d)[1]), "+f"((d)[2]), "+f"((d)[3])                \
        : "r"(A0), "r"(A1), "r"(A2), "r"(A3), "r"(B0), "r"(B1))

#define LDSM4(r0, r1, r2, r3, a)                                                \
    asm volatile("ldmatrix.sync.aligned.m8n8.x4.shared.b16 {%0,%1,%2,%3}, [%4];" \
        : "=r"(r0), "=r"(r1), "=r"(r2), "=r"(r3) : "r"(a))

#define LDSM2(r0, r1, a)                                                        \
    asm volatile("ldmatrix.sync.aligned.m8n8.x2.shared.b16 {%0,%1}, [%2];"      \
        : "=r"(r0), "=r"(r1) : "r"(a))

// swizzled offset within a tile: row r (0..127), k16 subtile s, 16B half h
__device__ __forceinline__ uint32_t swz(int r, int s, int h) {
    return (uint32_t)(r * 64 + ((s ^ ((r >> 1) & 1)) << 5) + ((h ^ ((r >> 2) & 1)) << 4));
}

__global__ __launch_bounds__(256, 1) void gemm_mma_kernel(const float* __restrict__ b1) {
    extern __shared__ char dyn[];
    const uint32_t sb = smem_u32(dyn);

    const int b  = blockIdx.y;
    const int c0 = (blockIdx.x & 1) * 128;
    const int o0 = ((blockIdx.x >> 1) & 1) * 128;
    const int z  = blockIdx.x >> 2;
    const int kbase = z * 512;

    const int tid  = threadIdx.x;
    const int lane = tid & 31;
    const int wid  = tid >> 5;
    const int wm   = wid & 1;      // 64-row (c) half
    const int wn   = wid >> 1;     // 32-col (o) quarter
    const int g    = lane >> 2;
    const int tq   = lane & 3;

    // loader lane constants
    const int lr    = lane >> 3;   // row-within-iter
    const int chunk = lane & 7;    // 16B chunk within row-stage (4 k each)
    const int s_ch  = chunk >> 2, h_ch = (chunk >> 1) & 1, q_ch = chunk & 1;

    float acc[4][4][4];
#pragma unroll
    for (int mi = 0; mi < 4; ++mi)
#pragma unroll
        for (int ni = 0; ni < 4; ++ni)
#pragma unroll
            for (int r = 0; r < 4; ++r) acc[mi][ni][r] = 0.f;

    uint4 lv[8];

    auto ldg_stage = [&](int ks) {
        const int kg = kbase + ks * 32;
#pragma unroll
        for (int it = 0; it < 8; ++it) {
            const int rowid = (wid * 8 + it) * 4 + lr;
            const int mat = rowid >> 7, r = rowid & 127;
            const uint32_t* src = mat ? (g_BP + ((size_t)(b * 256 + o0 + r) << 10))
                                      : (g_AP + ((size_t)(b * 256 + c0 + r) << 10));
            lv[it] = *(const uint4*)(src + kg + chunk * 4);
        }
    };

    auto sts_stage = [&](int buf) {
#pragma unroll
        for (int it = 0; it < 8; ++it) {
            const int rowid = (wid * 8 + it) * 4 + lr;
            const int mat = rowid >> 7, r = rowid & 127;
            uint32_t hi01 = __byte_perm(lv[it].x, lv[it].y, 0x7632);
            uint32_t lo01 = __byte_perm(lv[it].x, lv[it].y, 0x5410);
            uint32_t hi23 = __byte_perm(lv[it].z, lv[it].w, 0x7632);
            uint32_t lo23 = __byte_perm(lv[it].z, lv[it].w, 0x5410);
            const uint32_t off = swz(r, s_ch, h_ch) + q_ch * 8;
            const uint32_t hbase = sb + (uint32_t)(buf * 4 + mat * 2) * GTILE + off;
            asm volatile("st.shared.v2.b32 [%0], {%1,%2};"
                         :: "r"(hbase), "r"(hi01), "r"(hi23) : "memory");
            asm volatile("st.shared.v2.b32 [%0], {%1,%2};"
                         :: "r"(hbase + GTILE), "r"(lo01), "r"(lo23) : "memory");
        }
    };

    auto compute16 = [&](int buf, int s) {
        const uint32_t ah_t = sb + (uint32_t)(buf * 4 + 0) * GTILE;
        const uint32_t bh_t = sb + (uint32_t)(buf * 4 + 2) * GTILE;
        const int arow = wm * 64 + (lane & 15);
        const int ah = lane >> 4;
        const int brow = wn * 32 + (lane & 7);
        const int bh = (lane >> 3) & 1;

        uint32_t aH[4][4], aL[4][4];
#pragma unroll
        for (int mi = 0; mi < 4; ++mi) {
            const uint32_t off = swz(arow + mi * 16, s, ah);
            LDSM4(aH[mi][0], aH[mi][1], aH[mi][2], aH[mi][3], ah_t + off);
            LDSM4(aL[mi][0], aL[mi][1], aL[mi][2], aL[mi][3], ah_t + GTILE + off);
        }
        uint32_t bH[4][2], bL[4][2];
#pragma unroll
        for (int ni = 0; ni < 4; ++ni) {
            const uint32_t off = swz(brow + ni * 8, s, bh);
            LDSM2(bH[ni][0], bH[ni][1], bh_t + off);
            LDSM2(bL[ni][0], bL[ni][1], bh_t + GTILE + off);
        }
#pragma unroll
        for (int mi = 0; mi < 4; ++mi)
#pragma unroll
            for (int ni = 0; ni < 4; ++ni) {
                MMA_BF16(acc[mi][ni], aH[mi][0], aH[mi][1], aH[mi][2], aH[mi][3],
                         bH[ni][0], bH[ni][1]);
                MMA_BF16(acc[mi][ni], aH[mi][0], aH[mi][1], aH[mi][2], aH[mi][3],
                         bL[ni][0], bL[ni][1]);
                MMA_BF16(acc[mi][ni], aL[mi][0], aL[mi][1], aL[mi][2], aL[mi][3],
                         bH[ni][0], bH[ni][1]);
            }
    };

    ldg_stage(0);
    sts_stage(0);
    __syncthreads();

    for (int ks = 0; ks < NSTAGE; ++ks) {
        const int buf = ks & 1;
        if (ks + 1 < NSTAGE) ldg_stage(ks + 1);
        compute16(buf, 0);
        compute16(buf, 1);
        if (ks + 1 < NSTAGE) sts_stage(buf ^ 1);
        __syncthreads();
    }

    float* Y = z ? g_y2 : g_y;
#pragma unroll
    for (int ni = 0; ni < 4; ++ni) {
        const int oc = o0 + wn * 32 + ni * 8 + 2 * tq;
        float2 bias = make_float2(0.f, 0.f);
        if (z == 0) bias = *(const float2*)(b1 + oc);
#pragma unroll
        for (int mi = 0; mi < 4; ++mi) {
            const int crow = c0 + wm * 64 + mi * 16 + g;
            float2 v0 = make_float2(acc[mi][ni][0] + bias.x, acc[mi][ni][1] + bias.y);
            float2 v1 = make_float2(acc[mi][ni][2] + bias.x, acc[mi][ni][3] + bias.y);
            *(float2*)(Y + ((size_t)b * C2 + crow)     * OUTC + oc) = v0;
            *(float2*)(Y + ((size_t)b * C2 + crow + 8) * OUTC + oc) = v1;
        }
    }
}

// ---------------- BN batch stats -------------------------------------------------
__global__ __launch_bounds__(256) void stats_kernel() {
    const int c = blockIdx.x;
    const int o = threadIdx.x;
    float s = 0.f, s2 = 0.f;
#pragma unroll
    for (int b = 0; b < BB; ++b) {
        size_t idx = ((size_t)b * C2 + c) * OUTC + o;
        float v = g_y[idx] + g_y2[idx];
        s += v;
        s2 = fmaf(v, v, s2);
    }
    __shared__ float rs[256], rq[256];
    rs[o] = s; rq[o] = s2;
    __syncthreads();
    for (int st = 128; st > 0; st >>= 1) {
        if (o < st) { rs[o] += rs[o + st]; rq[o] += rq[o + st]; }
        __syncthreads();
    }
    if (o == 0) {
        float mean = rs[0] * (1.f / 4096.f);
        float var  = rq[0] * (1.f / 4096.f) - mean * mean;
        g_mean[c] = mean;
        g_rstd[c] = rsqrtf(var + 1e-5f);
    }
}

// ---------------- BN apply + ReLU + transpose ------------------------------------
__global__ void epilogue_kernel(const float* __restrict__ gamma,
                                const float* __restrict__ beta,
                                float* __restrict__ out) {
    __shared__ float tile[32][33];
    const int b = blockIdx.z, c0 = blockIdx.x * 32, o0 = blockIdx.y * 32;
    const int tx = threadIdx.x, ty = threadIdx.y;
#pragma unroll
    for (int i = 0; i < 4; ++i) {
        int c = c0 + ty + i * 8;
        size_t idx = ((size_t)b * C2 + c) * OUTC + o0 + tx;
        float v = g_y[idx] + g_y2[idx];
        v = fmaf(gamma[c] * g_rstd[c], v - g_mean[c], beta[c]);
        tile[ty + i * 8][tx] = fmaxf(v, 0.f);
    }
    __syncthreads();
#pragma unroll
    for (int i = 0; i < 4; ++i) {
        int o = o0 + ty + i * 8;
        out[((size_t)b * OUTC + o) * C2 + c0 + tx] = tile[tx][ty + i * 8];
    }
}

// ---------------- launch ----------------------------------------------------------
extern "C" void kernel_launch(void* const* d_in, const int* in_sizes, int n_in,
                              void* d_out, int out_size) {
    const float* x2    = (const float*)d_in[1];
    const float* xyz1  = (const float*)d_in[2];
    const float* xyz2  = (const float*)d_in[3];
    const float* W1    = (const float*)d_in[4];
    const float* b1    = (const float*)d_in[5];
    const float* gamma = (const float*)d_in[6];
    const float* beta  = (const float*)d_in[7];
    float* out = (float*)d_out;

    uint32_t* apD; cudaGetSymbolAddress((void**)&apD, g_AP);
    uint32_t* bpD; cudaGetSymbolAddress((void**)&bpD, g_BP);
    float*    tD;  cudaGetSymbolAddress((void**)&tD,  g_T);

    const int dyn_smem = 8 * GTILE;   // 64 KB
    cudaFuncSetAttribute(gemm_mma_kernel, cudaFuncAttributeMaxDynamicSharedMemorySize, dyn_smem);

    conv_kernel<<<dim3(32, 8, BB), dim3(32, 8)>>>(x2, apD);            // idx 0
    knn_kernel<<<dim3(N1 / 256, BB), 256>>>(xyz1, xyz2);               // idx 1
    prep_kernel<<<BB + 256, 1024>>>(W1);                               // idx 2
    tbuild_kernel<<<dim3(N2 / 4, BB), 256>>>();                        // idx 3 <- profiled
    conv_kernel<<<dim3(32, 8, BB), dim3(32, 8)>>>(tD, bpD);            // idx 4
    gemm_mma_kernel<<<dim3(8, BB), 256, dyn_smem>>>(b1);               // idx 5
    stats_kernel<<<C2, 256>>>();                                       // idx 6
    epilogue_kernel<<<dim3(8, 8, BB), dim3(32, 8)>>>(gamma, beta, out); // idx 7
}